// round 12
// baseline (speedup 1.0000x reference)
#include <cuda_runtime.h>
#include <math.h>

#define NN 512
#define SD 64
#define ED 16
#define LL 5
#define DOUT 97
#define EPG 4032
#define NCTA 128
#define TPB 512
#define RS 116

#define OFF_V (NN*SD)
#define OFF_E (OFF_V + NN*48)
#define OFF_P (OFF_E + 8*EPG*ED)

// ---- shared layout (float offsets) ----
#define SH_W2T   0        /* 64*68 */
#define SH_W2T2  4352     /* 33*68 */
#define SH_W1TT  6596     /* 64*20 : W1 tail per-col transposed */
#define SH_WPS   7876     /* 256 */
#define SH_W1S   8132     /* 8192 : W1 rows 0..127 (reused Wm1|Wm2 pre-gsync) */
#define SH_CJ    16324    /* 4096 */
#define SH_CI    20420    /* 256 */
#define SH_V     20676    /* 3072 */
#define SH_P     23748    /* 192 */
#define SH_PN    23940    /* 192 */
#define SH_F     24132    /* 1024 */
#define SH_TB    25156    /* 40 */
#define SH_H     25196    /* 4*140 */
#define SH_RED   25756    /* 32 */
#define SH_AB    25788    /* 4*52 */
#define SH_HW    25996    /* 16*64 */
#define SH_EI    27020    /* 4096 */
#define SH_REC   31116    /* 160*116 */
#define SH_IT    49676    /* 256 ints */
#define SH_NBR   49932    /* 256 ints */
#define SH_OFF   50188    /* 8 ints */
#define SH_CNT   50196    /* 4 ints */
#define SH_LI    50200    /* 4 ints */
#define SH_WCNT  50204    /* 8 ints */
#define SH_WPRE  50212    /* 1024 : Wpre own buffer */
#define SH_TOTAL 51236
#define SMEM_BYTES (SH_TOTAL*4)

// ---------------- device state ----------------
__device__ float g_cj[NN*SD];
__device__ float g_vn[NN*48];
__device__ float g_p[2][NN*3];
__device__ float g_pn[NN*3];
__device__ float g_f[NN*ED];
__device__ int   g_map[NN];
__device__ unsigned int g_ctr;

__device__ __forceinline__ void bar64(int grp) {
    asm volatile("bar.sync %0, 64;" :: "r"(grp + 1) : "memory");
}
__device__ __forceinline__ void bar128(int grp) {
    asm volatile("bar.sync %0, 128;" :: "r"(grp + 5) : "memory");
}
__device__ __forceinline__ float silu(float x) {
    return x * (1.0f / (1.0f + __expf(-x)));
}
__device__ __forceinline__ void gsync(unsigned int target) {
    __syncthreads();
    __threadfence();
    if (threadIdx.x == 0) {
        atomicAdd(&g_ctr, 1u);
        volatile unsigned int* c = &g_ctr;
        while (*c < target) { }
        __threadfence();
    }
    __syncthreads();
}

// ---------------- init: degree-balanced node->CTA map ----------------
__global__ void k_init(const float* __restrict__ p) {
    __shared__ int cnt_s[NN];
    int n = threadIdx.x;
    int gb = (n >> 6) << 6;
    float px = p[n*3], py = p[n*3+1], pz = p[n*3+2];
    int cnt = 0;
    for (int j = 0; j < 64; j++) {
        int jg = gb + j;
        if (jg == n) continue;
        float dx = p[jg*3]-px, dy = p[jg*3+1]-py, dz = p[jg*3+2]-pz;
        if (dx*dx + dy*dy + dz*dz < 25.0f) cnt++;
    }
    cnt_s[n] = cnt;
    __syncthreads();
    int rank = 0;
    for (int j = 0; j < 64; j++) {
        int cj = cnt_s[gb + j];
        if (cj > cnt || (cj == cnt && (gb + j) < n)) rank++;
    }
    int round = rank >> 4, pos = rank & 15;
    int cta = (round & 1) ? (15 - pos) : pos;
    g_map[(((n >> 6)*16 + cta) << 2) + round] = n;
    g_p[0][n*3] = px; g_p[0][n*3+1] = py; g_p[0][n*3+2] = pz;
    if (n == 0) g_ctr = 0u;
}

__global__ void __launch_bounds__(TPB, 1)
k_fused(const float* __restrict__ s_in, const float* __restrict__ v_in,
        const float* __restrict__ p_in, const float* __restrict__ ea,
        const float* __restrict__ ln_g, const float* __restrict__ ln_b,
        const float* __restrict__ W1,  const float* __restrict__ b1,
        const float* __restrict__ W2,  const float* __restrict__ b2,
        const float* __restrict__ Wm1, const float* __restrict__ bm1,
        const float* __restrict__ Wm2, const float* __restrict__ bm2,
        const float* __restrict__ Wpre,const float* __restrict__ bpre,
        const float* __restrict__ Wpost,const float* __restrict__ bpost,
        float* __restrict__ out)
{
    extern __shared__ float sh[];
    int* shi = (int*)sh;
    const int tx   = threadIdx.x;
    const int grp  = tx >> 7;
    const int t128 = tx & 127;
    const int t    = tx & 63;
    const int lane = tx & 31;
    const int widx = tx >> 5;
    const bool lower = (t128 < 64);
    const int wrp  = t >> 5;
    const int gg   = blockIdx.x >> 4;
    const int cbase = gg << 6;
    const int i    = g_map[blockIdx.x*4 + grp];
    const int li   = i & 63;
    unsigned int epoch = 0;
    float* shHb = sh + SH_H + grp*140;

    float s_reg = s_in[i*SD + t];
    float v_reg = (t < 48) ? v_in[i*48 + t] : 0.0f;

    // -------- adjacency (lower 64 per node) --------
    if (lower) {
        float pix = p_in[i*3], piy = p_in[i*3+1], piz = p_in[i*3+2];
        int jg = cbase + t;
        float dx = p_in[jg*3]-pix, dy = p_in[jg*3+1]-piy, dz = p_in[jg*3+2]-piz;
        bool ok = (jg != i) && (dx*dx + dy*dy + dz*dz < 25.0f);
        unsigned m = __ballot_sync(0xffffffffu, ok);
        if (lane == 0) shi[SH_WCNT + grp*2 + wrp] = __popc(m);
        bar64(grp);
        int base = (wrp == 1) ? shi[SH_WCNT + grp*2] : 0;
        if (ok) shi[SH_NBR + grp*64 + base + __popc(m & ((1u << lane) - 1u))] = t;
        if (t == 0) {
            shi[SH_CNT + grp] = shi[SH_WCNT + grp*2] + shi[SH_WCNT + grp*2 + 1];
            shi[SH_LI + grp] = li;
        }
        bar64(grp);
    }
    __syncthreads();
    if (tx == 0) {
        int o = 0; shi[SH_OFF] = 0;
        #pragma unroll
        for (int n = 0; n < 4; n++) { o += shi[SH_CNT + n]; shi[SH_OFF + n + 1] = o; }
    }
    __syncthreads();
    const int cnt = shi[SH_CNT + grp];
    const float dinv = 1.0f / fmaxf((float)cnt, 1.0f);
    if (lower && t < cnt)
        shi[SH_IT + shi[SH_OFF + grp] + t] = (grp << 6) | shi[SH_NBR + grp*64 + t];
    __syncthreads();
    const int nit = shi[SH_OFF + 4];

    // E slice into smem
    for (int idx = tx; idx < nit*ED; idx += TPB) {
        int item = shi[SH_IT + (idx >> 4)];
        int c = idx & 15;
        int ig2 = item >> 6, j = item & 63;
        int lio = shi[SH_LI + ig2];
        int e = gg*EPG + lio*63 + j - (j > lio ? 1 : 0);
        sh[SH_EI + idx] = ea[(size_t)e*ED + c];
    }

    // -------- layers --------
    for (int l = 0; l < LL; l++) {
        const int pin = l & 1, pout = pin ^ 1;

        __syncthreads();
        {
            const float4* w1g = (const float4*)(W1 + (size_t)l*146*SD);
            float4* w1s = (float4*)(sh + SH_W1S);
            for (int idx = tx; idx < 128*SD/4; idx += TPB) w1s[idx] = w1g[idx];
        }
        __syncthreads();

        // ---- node_pre ----
        if (lower) {
            float xs = s_reg, xq = s_reg*s_reg;
            float xv = (t < 48) ? v_reg*v_reg : 0.0f;
            #pragma unroll
            for (int o = 16; o; o >>= 1) {
                xs += __shfl_down_sync(0xffffffffu, xs, o);
                xq += __shfl_down_sync(0xffffffffu, xq, o);
                xv += __shfl_down_sync(0xffffffffu, xv, o);
            }
            bar64(grp);
            if (lane == 0) {
                float* r = sh + SH_RED + grp*8 + wrp*3;
                r[0] = xs; r[1] = xq; r[2] = xv;
            }
            bar64(grp);
            const float* r = sh + SH_RED + grp*8;
            float mu   = (r[0] + r[3]) * (1.0f/64);
            float var  = (r[1] + r[4]) * (1.0f/64) - mu*mu;
            float vinv = rsqrtf((r[2] + r[5]) * (1.0f/16) + 1e-6f);
            s_reg = (s_reg - mu) * rsqrtf(fmaxf(var, 0.0f) + 1e-6f) * ln_g[l*SD + t] + ln_b[l*SD + t];
            shHb[t] = s_reg;
            if (t < 48) { v_reg *= vinv; g_vn[i*48 + t] = v_reg; }
            if (t < 3) {
                float p0 = g_p[pin][i*3], p1 = g_p[pin][i*3+1], p2 = g_p[pin][i*3+2];
                float inv = rsqrtf(p0*p0 + p1*p1 + p2*p2);
                g_pn[i*3 + t] = g_p[pin][i*3 + t] * inv;
            }
        }
        bar128(grp);
        {
            int which = t128 >> 6;
            const float* w1s = sh + SH_W1S + which*4096;
            float a0 = which ? 0.0f : b1[l*SD + t];
            float a1 = 0.0f;
            #pragma unroll 8
            for (int k = 0; k < SD; k += 2) {
                a0 += shHb[k]   * w1s[k*64 + t];
                a1 += shHb[k+1] * w1s[(k+1)*64 + t];
            }
            float acc = a0 + a1;
            if (which == 0) sh[SH_CI + grp*64 + t] = acc;
            else            g_cj[i*SD + t] = acc;
        }

        // ---- stage ALL WEIGHTS pre-gsync (overlaps barrier wait) ----
        __syncthreads();   // W1S fully read by ci/cj matvec before Wm overwrite
        {
            const float* w2g = W2 + (size_t)l*SD*DOUT;
            for (int idx = tx; idx < SD*DOUT; idx += TPB) {
                int kk = idx / DOUT, col = idx - kk*DOUT;
                float w = w2g[idx];
                if (col < 64) sh[SH_W2T + col*68 + kk] = w;
                else          sh[SH_W2T2 + (col-64)*68 + kk] = w;
            }
            for (int idx = tx; idx < 64*18; idx += TPB) {
                int col = idx / 18, row = idx - col*18;
                sh[SH_W1TT + col*20 + row] = W1[(size_t)l*146*SD + (128+row)*SD + col];
            }
            for (int idx = tx; idx < 33; idx += TPB)
                sh[SH_TB + idx] = b2[l*DOUT + 64 + idx];
            if (l > 0) {
                for (int idx = tx; idx < ED*ED; idx += TPB)
                    sh[SH_WPS + idx] = Wpost[(l-1)*ED*ED + idx];
            }
            if (l < LL-1) {
                const float4* m1 = (const float4*)(Wm1 + (size_t)l*SD*SD);
                const float4* m2 = (const float4*)(Wm2 + (size_t)l*SD*SD);
                float4* w1s = (float4*)(sh + SH_W1S);
                for (int idx = tx; idx < SD*SD/4; idx += TPB) {
                    w1s[idx] = m1[idx];
                    w1s[SD*SD/4 + idx] = m2[idx];
                }
            }
            const float4* wpg = (const float4*)(Wpre + (size_t)l*SD*ED);
            float4* wps = (float4*)(sh + SH_WPRE);
            for (int idx = tx; idx < SD*ED/4; idx += TPB) wps[idx] = wpg[idx];
        }

        gsync(++epoch * NCTA);   // publishes cj/vn/pn/p(l) + f(l-1)

        // ---- stage DYNAMICS only (post-gsync) ----
        {
            const float4* cjg = (const float4*)(g_cj + cbase*SD);
            float4* cjs = (float4*)(sh + SH_CJ);
            for (int idx = tx; idx < 64*SD/4; idx += TPB) cjs[idx] = cjg[idx];
            if (l > 0) {
                const float4* vg = (const float4*)(g_vn + cbase*48);
                float4* vs = (float4*)(sh + SH_V);
                for (int idx = tx; idx < 64*48/4; idx += TPB) vs[idx] = vg[idx];
                const float4* fg = (const float4*)(g_f + cbase*ED);
                float4* fs = (float4*)(sh + SH_F);
                for (int idx = tx; idx < 64*ED/4; idx += TPB) fs[idx] = fg[idx];
            }
            for (int idx = tx; idx < 192; idx += TPB) {
                sh[SH_P + idx]  = g_p[pin][cbase*3 + idx];
                sh[SH_PN + idx] = g_pn[cbase*3 + idx];
            }
        }
        __syncthreads();

        // ---- edge update (layer l-1): 32 half-warp processors ----
        if (l > 0) {
            int hw = lane >> 4, e = lane & 15;
            float bp = bpost[(l-1)*ED + e];
            for (int b = widx*2; b < nit; b += 32) {
                int k = b + hw;
                bool act = (k < nit);
                int sl = act ? k : 0;
                int item = shi[SH_IT + sl];
                int ig2 = item >> 6, j = item & 63;
                float x = sh[SH_F + shi[SH_LI + ig2]*ED + e] + sh[SH_F + j*ED + e];
                float tv = sh[SH_EI + sl*ED + e] + silu(x);
                float o = bp;
                #pragma unroll
                for (int m = 0; m < ED; m++) {
                    float tm = __shfl_sync(0xffffffffu, tv, (hw << 4) + m);
                    o += tm * sh[SH_WPS + m*ED + e];
                }
                if (act) sh[SH_EI + sl*ED + e] = o;
            }
        }
        __syncthreads();

        // ---- pair phase: flat items across 16 warps ----
        {
            float* hb = sh + SH_HW + widx*64;
            const float b2g = sh[SH_TB + 32];
            const float4* Ta4 = (const float4*)(sh + SH_W1TT + lane*20);
            const float4* Tb4 = (const float4*)(sh + SH_W1TT + (lane+32)*20);
            const float*  Ta  = sh + SH_W1TT + lane*20;
            const float*  Tb  = sh + SH_W1TT + (lane+32)*20;
            const float4* wc4 = (const float4*)(sh + SH_W2T2 + lane*68);

            for (int k = widx; k < nit; k += 16) {
                int item = shi[SH_IT + k];
                int ig2 = item >> 6, j = item & 63;
                int lio = shi[SH_LI + ig2];

                float pix = sh[SH_P + lio*3], piy = sh[SH_P + lio*3+1], piz = sh[SH_P + lio*3+2];
                float dx = sh[SH_P + j*3]-pix, dy = sh[SH_P + j*3+1]-piy, dz = sh[SH_P + j*3+2]-piz;
                float dd = sqrtf(fmaxf(dx*dx + dy*dy + dz*dz, 1e-6f));
                float ac = sh[SH_PN + lio*3]*sh[SH_PN + j*3]
                         + sh[SH_PN + lio*3+1]*sh[SH_PN + j*3+1]
                         + sh[SH_PN + lio*3+2]*sh[SH_PN + j*3+2];
                float env = 0.5f*(__cosf(dd*0.62831853f) + 1.0f);
                float ri = 1.0f/(1.0f + dd);
                float rnx = dx*ri, rny = dy*ri, rnz = dz*ri;

                const float4* Ep = (const float4*)(sh + SH_EI + k*ED);
                float4 E0 = Ep[0], E1 = Ep[1], E2 = Ep[2], E3 = Ep[3];

                float hvA = sh[SH_CI + ig2*64 + lane]      + sh[SH_CJ + j*SD + lane];
                float hvB = sh[SH_CI + ig2*64 + 32 + lane] + sh[SH_CJ + j*SD + 32 + lane];
                {
                    float4 w0 = Ta4[0], w1 = Ta4[1], w2 = Ta4[2], w3 = Ta4[3];
                    hvA += dd*w0.x + ac*w0.y + E0.x*w0.z + E0.y*w0.w
                         + E0.z*w1.x + E0.w*w1.y + E1.x*w1.z + E1.y*w1.w
                         + E1.z*w2.x + E1.w*w2.y + E2.x*w2.z + E2.y*w2.w
                         + E2.z*w3.x + E2.w*w3.y + E3.x*w3.z + E3.y*w3.w
                         + E3.z*Ta[16] + E3.w*Ta[17];
                }
                {
                    float4 w0 = Tb4[0], w1 = Tb4[1], w2 = Tb4[2], w3 = Tb4[3];
                    hvB += dd*w0.x + ac*w0.y + E0.x*w0.z + E0.y*w0.w
                         + E0.z*w1.x + E0.w*w1.y + E1.x*w1.z + E1.y*w1.w
                         + E1.z*w2.x + E1.w*w2.y + E2.x*w2.z + E2.y*w2.w
                         + E2.z*w3.x + E2.w*w3.y + E3.x*w3.z + E3.y*w3.w
                         + E3.z*Tb[16] + E3.w*Tb[17];
                }
                float hpA = silu(hvA)*env;
                float hpB = silu(hvB)*env;

                float gcp = hpA*sh[SH_W2T2 + 32*68 + lane] + hpB*sh[SH_W2T2 + 32*68 + 32 + lane];
                #pragma unroll
                for (int o = 16; o; o >>= 1) gcp += __shfl_xor_sync(0xffffffffu, gcp, o);
                float gc = gcp + b2g*env;

                hb[lane] = hpA; hb[32 + lane] = hpB;
                __syncwarp();
                const float4* h4 = (const float4*)hb;
                float a0=0,a1=0,a2=0,a3=0;
                #pragma unroll
                for (int q = 0; q < 16; q++) {
                    float4 h = h4[q];
                    float4 w = wc4[q];
                    a0 += h.x*w.x; a1 += h.y*w.y;
                    a2 += h.z*w.z; a3 += h.w*w.w;
                }
                float tailv = (a0+a1)+(a2+a3) + sh[SH_TB + lane]*env;
                __syncwarp();

                int d = lane & 15;
                float gr = __shfl_sync(0xffffffffu, tailv, d);
                float gv = __shfl_sync(0xffffffffu, tailv, 16 + d);
                float rnA = (lane < 16) ? rnx : rny;
                float vA = rnA*gr;
                float vB = rnz*gr;
                if (l > 0) {
                    vA += sh[SH_V + j*48 + lane]*gv;
                    if (lane < 16) vB += sh[SH_V + j*48 + 32 + lane]*gv;
                }
                float* rec = sh + SH_REC + k*RS;
                rec[lane]      = hpA;
                rec[32 + lane] = hpB;
                rec[64 + lane] = vA;
                if (lane < 16) rec[96 + lane] = vB;
                if (lane < 3)  rec[112 + lane] = gc * ((lane==0)?rnx:((lane==1)?rny:rnz));
                if (lane == 0) rec[115] = env;
            }
        }
        __syncthreads();

        // ---- owner reduction across all 128 threads ----
        {
            int o0 = shi[SH_OFF + grp], o1 = shi[SH_OFF + grp + 1];
            float a0 = 0.0f, a1 = 0.0f;
            if (t128 < 116) {
                int k = o0;
                for (; k + 1 < o1; k += 2) {
                    a0 += sh[SH_REC + k*RS + t128];
                    a1 += sh[SH_REC + (k+1)*RS + t128];
                }
                if (k < o1) a0 += sh[SH_REC + k*RS + t128];
            }
            float acc = a0 + a1;
            if (lower) shHb[t] = acc;                                // henv
            else if (t128 < 116) sh[SH_AB + grp*52 + (t128-64)] = acc;
            bar128(grp);
            if (lower) {
                float envs = sh[SH_AB + grp*52 + 51];
                const float4* hs = (const float4*)shHb;
                const float4* wc = (const float4*)(sh + SH_W2T + t*68);
                float b0=0,b1v=0,b2v=0,b3=0;
                #pragma unroll
                for (int q = 0; q < 16; q++) {
                    float4 h4 = hs[q];
                    float4 w4 = wc[q];
                    b0 += h4.x*w4.x; b1v += h4.y*w4.y;
                    b2v += h4.z*w4.z; b3 += h4.w*w4.w;
                }
                s_reg += (b0+b1v)+(b2v+b3) + b2[l*DOUT + t]*envs;
                float accb = (t < 51) ? sh[SH_AB + grp*52 + t] : 0.0f;
                if (t < 48) v_reg += accb * dinv;
                if (t >= 48 && t < 51)
                    g_p[pout][i*3 + (t-48)] = sh[SH_P + li*3 + (t-48)] + accb * dinv;
            }
            bar128(grp);
        }

        // ---- node_post (lower 64 only) ----
        if (lower) {
            if (l < LL-1) {
                shHb[t] = s_reg;
                bar64(grp);
                const float* wm1 = sh + SH_W1S;
                float m0 = bm1[l*SD + t], m1 = 0.0f;
                #pragma unroll 8
                for (int kk = 0; kk < SD; kk += 2) {
                    m0 += shHb[kk]   * wm1[kk*SD + t];
                    m1 += shHb[kk+1] * wm1[(kk+1)*SD + t];
                }
                float hm = silu(m0 + m1);
                shHb[68 + t] = hm;
                bar64(grp);
                const float* wm2 = sh + SH_W1S + SD*SD;
                float q0 = bm2[l*SD + t], q1 = 0.0f;
                #pragma unroll 8
                for (int kk = 0; kk < SD; kk += 2) {
                    q0 += shHb[68+kk]   * wm2[kk*SD + t];
                    q1 += shHb[68+kk+1] * wm2[(kk+1)*SD + t];
                }
                s_reg += q0 + q1;
                bar64(grp);
            }
            shHb[t] = s_reg;
            bar64(grp);
            if (t < ED) {
                const float* wp = sh + SH_WPRE;
                float f0 = bpre[l*ED + t], f1 = 0.0f;
                #pragma unroll 8
                for (int kk = 0; kk < SD; kk += 2) {
                    f0 += shHb[kk]   * wp[kk*ED + t];
                    f1 += shHb[kk+1] * wp[(kk+1)*ED + t];
                }
                g_f[i*ED + t] = f0 + f1;
            }
        }
    }

    gsync(++epoch * NCTA);   // publish f(LL-1)

    // ---- final edge update ----
    {
        const float4* fg = (const float4*)(g_f + cbase*ED);
        float4* fs = (float4*)(sh + SH_F);
        for (int idx = tx; idx < 64*ED/4; idx += TPB) fs[idx] = fg[idx];
        for (int idx = tx; idx < ED*ED; idx += TPB)
            sh[SH_WPS + idx] = Wpost[(LL-1)*ED*ED + idx];
    }
    __syncthreads();
    {
        int hw = lane >> 4, e = lane & 15;
        float bp = bpost[(LL-1)*ED + e];
        for (int b = widx*2; b < nit; b += 32) {
            int k = b + hw;
            bool act = (k < nit);
            int sl = act ? k : 0;
            int item = shi[SH_IT + sl];
            int ig2 = item >> 6, j = item & 63;
            float x = sh[SH_F + shi[SH_LI + ig2]*ED + e] + sh[SH_F + j*ED + e];
            float tv = sh[SH_EI + sl*ED + e] + silu(x);
            float o = bp;
            #pragma unroll
            for (int m = 0; m < ED; m++) {
                float tm = __shfl_sync(0xffffffffu, tv, (hw << 4) + m);
                o += tm * sh[SH_WPS + m*ED + e];
            }
            if (act) sh[SH_EI + sl*ED + e] = o;
        }
    }
    __syncthreads();

    // -------- output --------
    if (lower) {
        out[i*SD + t] = s_reg;
        if (t < 48) out[OFF_V + i*48 + t] = v_reg;
        if (t < 3)  out[OFF_P + i*3 + t] = g_p[LL & 1][i*3 + t];
    }
    for (int idx = tx; idx < nit*ED; idx += TPB) {
        int item = shi[SH_IT + (idx >> 4)];
        int c = idx & 15;
        int ig2 = item >> 6, j = item & 63;
        int lio = shi[SH_LI + ig2];
        int e = gg*EPG + lio*63 + j - (j > lio ? 1 : 0);
        out[OFF_E + (size_t)e*ED + c] = sh[SH_EI + idx];
    }
    {
        const int e0 = blockIdx.x * (8*EPG / NCTA);
        for (int q = tx; q < (8*EPG/NCTA)*ED; q += TPB) {
            int e = e0 + (q >> 4), c = q & 15;
            int gg2 = e / EPG, rem = e - gg2*EPG;
            int si = rem / 63, t63 = rem - si*63;
            int ti = t63 + (t63 >= si ? 1 : 0);
            int a = gg2*64 + si, b = gg2*64 + ti;
            float dx = p_in[a*3]   - p_in[b*3];
            float dy = p_in[a*3+1] - p_in[b*3+1];
            float dz = p_in[a*3+2] - p_in[b*3+2];
            if (!(dx*dx + dy*dy + dz*dz < 25.0f))
                out[OFF_E + (size_t)e*ED + c] = ea[(size_t)e*ED + c];
        }
    }
}

// ---------------- launch ----------------
extern "C" void kernel_launch(void* const* d_in, const int* in_sizes, int n_in,
                              void* d_out, int out_size) {
    const float* s    = (const float*)d_in[0];
    const float* v    = (const float*)d_in[1];
    const float* p    = (const float*)d_in[2];
    const float* ea   = (const float*)d_in[3];
    const float* ln_g = (const float*)d_in[6];
    const float* ln_b = (const float*)d_in[7];
    const float* W1   = (const float*)d_in[8];
    const float* b1   = (const float*)d_in[9];
    const float* W2   = (const float*)d_in[10];
    const float* b2   = (const float*)d_in[11];
    const float* Wm1  = (const float*)d_in[12];
    const float* bm1  = (const float*)d_in[13];
    const float* Wm2  = (const float*)d_in[14];
    const float* bm2  = (const float*)d_in[15];
    const float* Wpre = (const float*)d_in[16];
    const float* bpre = (const float*)d_in[17];
    const float* Wpost= (const float*)d_in[18];
    const float* bpost= (const float*)d_in[19];
    float* out = (float*)d_out;

    cudaFuncSetAttribute(k_fused, cudaFuncAttributeMaxDynamicSharedMemorySize, SMEM_BYTES);
    k_init<<<1, NN>>>(p);
    k_fused<<<NCTA, TPB, SMEM_BYTES>>>(s, v, p, ea, ln_g, ln_b, W1, b1, W2, b2,
                                       Wm1, bm1, Wm2, bm2, Wpre, bpre, Wpost, bpost, out);
}

// round 13
// speedup vs baseline: 1.0011x; 1.0011x over previous
#include <cuda_runtime.h>
#include <math.h>

#define NN 512
#define SD 64
#define ED 16
#define LL 5
#define DOUT 97
#define EPG 4032
#define NCTA 128
#define TPB 512
#define RS 116

#define OFF_V (NN*SD)
#define OFF_E (OFF_V + NN*48)
#define OFF_P (OFF_E + 8*EPG*ED)

// ---- shared layout (float offsets) ----
#define SH_W2T   0        /* 64*68 */
#define SH_W2T2  4352     /* 33*68 */
#define SH_W1TT  6596     /* 64*20 : W1 tail per-col transposed */
#define SH_WPS   7876     /* 256 */
#define SH_W1S   8132     /* 8192 : W1 rows 0..127 (reused Wm1|Wm2 pre-gsync) */
#define SH_CJ    16324    /* 4096 */
#define SH_CI    20420    /* 256 */
#define SH_V     20676    /* 3072 */
#define SH_P     23748    /* 192 */
#define SH_PN    23940    /* 192 */
#define SH_F     24132    /* 1024 */
#define SH_TB    25156    /* 40 */
#define SH_H     25196    /* 4*140 */
#define SH_RED   25756    /* 32 */
#define SH_AB    25788    /* 4*52 */
#define SH_HW    25996    /* 16*64 */
#define SH_EI    27020    /* 4096 */
#define SH_REC   31116    /* 160*116 */
#define SH_IT    49676    /* 256 ints */
#define SH_NBR   49932    /* 256 ints */
#define SH_OFF   50188    /* 8 ints */
#define SH_CNT   50196    /* 4 ints */
#define SH_LI    50200    /* 4 ints */
#define SH_WCNT  50204    /* 8 ints */
#define SH_WPRE  50212    /* 1024 : Wpre own buffer */
#define SH_TOTAL 51236
#define SMEM_BYTES (SH_TOTAL*4)

// ---------------- device state ----------------
__device__ float g_cj[NN*SD];
__device__ float g_vn[NN*48];
__device__ float g_p[2][NN*3];
__device__ float g_pn[NN*3];
__device__ float g_f[NN*ED];
__device__ int   g_map[NN];
__device__ unsigned int g_ctr;

__device__ __forceinline__ void bar64(int grp) {
    asm volatile("bar.sync %0, 64;" :: "r"(grp + 1) : "memory");
}
__device__ __forceinline__ void bar128(int grp) {
    asm volatile("bar.sync %0, 128;" :: "r"(grp + 5) : "memory");
}
__device__ __forceinline__ float silu(float x) {
    return x * (1.0f / (1.0f + __expf(-x)));
}
__device__ __forceinline__ void gsync(unsigned int target) {
    __syncthreads();
    __threadfence();
    if (threadIdx.x == 0) {
        atomicAdd(&g_ctr, 1u);
        volatile unsigned int* c = &g_ctr;
        while (*c < target) { }
        __threadfence();
    }
    __syncthreads();
}

// ---------------- init: degree-balanced node->CTA map ----------------
__global__ void k_init(const float* __restrict__ p) {
    __shared__ int cnt_s[NN];
    int n = threadIdx.x;
    int gb = (n >> 6) << 6;
    float px = p[n*3], py = p[n*3+1], pz = p[n*3+2];
    int cnt = 0;
    for (int j = 0; j < 64; j++) {
        int jg = gb + j;
        if (jg == n) continue;
        float dx = p[jg*3]-px, dy = p[jg*3+1]-py, dz = p[jg*3+2]-pz;
        if (dx*dx + dy*dy + dz*dz < 25.0f) cnt++;
    }
    cnt_s[n] = cnt;
    __syncthreads();
    int rank = 0;
    for (int j = 0; j < 64; j++) {
        int cj = cnt_s[gb + j];
        if (cj > cnt || (cj == cnt && (gb + j) < n)) rank++;
    }
    int round = rank >> 4, pos = rank & 15;
    int cta = (round & 1) ? (15 - pos) : pos;
    g_map[(((n >> 6)*16 + cta) << 2) + round] = n;
    g_p[0][n*3] = px; g_p[0][n*3+1] = py; g_p[0][n*3+2] = pz;
    if (n == 0) g_ctr = 0u;
}

__global__ void __launch_bounds__(TPB, 1)
k_fused(const float* __restrict__ s_in, const float* __restrict__ v_in,
        const float* __restrict__ p_in, const float* __restrict__ ea,
        const float* __restrict__ ln_g, const float* __restrict__ ln_b,
        const float* __restrict__ W1,  const float* __restrict__ b1,
        const float* __restrict__ W2,  const float* __restrict__ b2,
        const float* __restrict__ Wm1, const float* __restrict__ bm1,
        const float* __restrict__ Wm2, const float* __restrict__ bm2,
        const float* __restrict__ Wpre,const float* __restrict__ bpre,
        const float* __restrict__ Wpost,const float* __restrict__ bpost,
        float* __restrict__ out)
{
    extern __shared__ float sh[];
    int* shi = (int*)sh;
    const int tx   = threadIdx.x;
    const int grp  = tx >> 7;
    const int t128 = tx & 127;
    const int t    = tx & 63;
    const int lane = tx & 31;
    const int widx = tx >> 5;
    const bool lower = (t128 < 64);
    const int wrp  = t >> 5;
    const int gg   = blockIdx.x >> 4;
    const int cbase = gg << 6;
    const int i    = g_map[blockIdx.x*4 + grp];
    const int li   = i & 63;
    unsigned int epoch = 0;
    float* shHb = sh + SH_H + grp*140;

    float s_reg = s_in[i*SD + t];
    float v_reg = (t < 48) ? v_in[i*48 + t] : 0.0f;

    // -------- adjacency (lower 64 per node) --------
    if (lower) {
        float pix = p_in[i*3], piy = p_in[i*3+1], piz = p_in[i*3+2];
        int jg = cbase + t;
        float dx = p_in[jg*3]-pix, dy = p_in[jg*3+1]-piy, dz = p_in[jg*3+2]-piz;
        bool ok = (jg != i) && (dx*dx + dy*dy + dz*dz < 25.0f);
        unsigned m = __ballot_sync(0xffffffffu, ok);
        if (lane == 0) shi[SH_WCNT + grp*2 + wrp] = __popc(m);
        bar64(grp);
        int base = (wrp == 1) ? shi[SH_WCNT + grp*2] : 0;
        if (ok) shi[SH_NBR + grp*64 + base + __popc(m & ((1u << lane) - 1u))] = t;
        if (t == 0) {
            shi[SH_CNT + grp] = shi[SH_WCNT + grp*2] + shi[SH_WCNT + grp*2 + 1];
            shi[SH_LI + grp] = li;
        }
        bar64(grp);
    }
    __syncthreads();
    if (tx == 0) {
        int o = 0; shi[SH_OFF] = 0;
        #pragma unroll
        for (int n = 0; n < 4; n++) { o += shi[SH_CNT + n]; shi[SH_OFF + n + 1] = o; }
    }
    __syncthreads();
    const int cnt = shi[SH_CNT + grp];
    const float dinv = 1.0f / fmaxf((float)cnt, 1.0f);
    if (lower && t < cnt)
        shi[SH_IT + shi[SH_OFF + grp] + t] = (grp << 6) | shi[SH_NBR + grp*64 + t];
    __syncthreads();
    const int nit = shi[SH_OFF + 4];

    // E slice into smem
    for (int idx = tx; idx < nit*ED; idx += TPB) {
        int item = shi[SH_IT + (idx >> 4)];
        int c = idx & 15;
        int ig2 = item >> 6, j = item & 63;
        int lio = shi[SH_LI + ig2];
        int e = gg*EPG + lio*63 + j - (j > lio ? 1 : 0);
        sh[SH_EI + idx] = ea[(size_t)e*ED + c];
    }

    // -------- layers --------
    for (int l = 0; l < LL; l++) {
        const int pin = l & 1, pout = pin ^ 1;

        __syncthreads();
        {
            const float4* w1g = (const float4*)(W1 + (size_t)l*146*SD);
            float4* w1s = (float4*)(sh + SH_W1S);
            for (int idx = tx; idx < 128*SD/4; idx += TPB) w1s[idx] = w1g[idx];
        }
        __syncthreads();

        // ---- node_pre ----
        if (lower) {
            float xs = s_reg, xq = s_reg*s_reg;
            float xv = (t < 48) ? v_reg*v_reg : 0.0f;
            #pragma unroll
            for (int o = 16; o; o >>= 1) {
                xs += __shfl_down_sync(0xffffffffu, xs, o);
                xq += __shfl_down_sync(0xffffffffu, xq, o);
                xv += __shfl_down_sync(0xffffffffu, xv, o);
            }
            bar64(grp);
            if (lane == 0) {
                float* r = sh + SH_RED + grp*8 + wrp*3;
                r[0] = xs; r[1] = xq; r[2] = xv;
            }
            bar64(grp);
            const float* r = sh + SH_RED + grp*8;
            float mu   = (r[0] + r[3]) * (1.0f/64);
            float var  = (r[1] + r[4]) * (1.0f/64) - mu*mu;
            float vinv = rsqrtf((r[2] + r[5]) * (1.0f/16) + 1e-6f);
            s_reg = (s_reg - mu) * rsqrtf(fmaxf(var, 0.0f) + 1e-6f) * ln_g[l*SD + t] + ln_b[l*SD + t];
            shHb[t] = s_reg;
            if (t < 48) { v_reg *= vinv; g_vn[i*48 + t] = v_reg; }
            if (t < 3) {
                float p0 = g_p[pin][i*3], p1 = g_p[pin][i*3+1], p2 = g_p[pin][i*3+2];
                float inv = rsqrtf(p0*p0 + p1*p1 + p2*p2);
                g_pn[i*3 + t] = g_p[pin][i*3 + t] * inv;
            }
        }
        bar128(grp);
        {
            int which = t128 >> 6;
            const float* w1s = sh + SH_W1S + which*4096;
            float a0 = which ? 0.0f : b1[l*SD + t];
            float a1 = 0.0f;
            #pragma unroll 8
            for (int k = 0; k < SD; k += 2) {
                a0 += shHb[k]   * w1s[k*64 + t];
                a1 += shHb[k+1] * w1s[(k+1)*64 + t];
            }
            float acc = a0 + a1;
            if (which == 0) sh[SH_CI + grp*64 + t] = acc;
            else            g_cj[i*SD + t] = acc;
        }

        // ---- stage ALL WEIGHTS pre-gsync (overlaps barrier wait) ----
        __syncthreads();
        {
            const float* w2g = W2 + (size_t)l*SD*DOUT;
            for (int idx = tx; idx < SD*DOUT; idx += TPB) {
                int kk = idx / DOUT, col = idx - kk*DOUT;
                float w = w2g[idx];
                if (col < 64) sh[SH_W2T + col*68 + kk] = w;
                else          sh[SH_W2T2 + (col-64)*68 + kk] = w;
            }
            for (int idx = tx; idx < 64*18; idx += TPB) {
                int col = idx / 18, row = idx - col*18;
                sh[SH_W1TT + col*20 + row] = W1[(size_t)l*146*SD + (128+row)*SD + col];
            }
            for (int idx = tx; idx < 33; idx += TPB)
                sh[SH_TB + idx] = b2[l*DOUT + 64 + idx];
            if (l > 0) {
                for (int idx = tx; idx < ED*ED; idx += TPB)
                    sh[SH_WPS + idx] = Wpost[(l-1)*ED*ED + idx];
            }
            if (l < LL-1) {
                const float4* m1 = (const float4*)(Wm1 + (size_t)l*SD*SD);
                const float4* m2 = (const float4*)(Wm2 + (size_t)l*SD*SD);
                float4* w1s = (float4*)(sh + SH_W1S);
                for (int idx = tx; idx < SD*SD/4; idx += TPB) {
                    w1s[idx] = m1[idx];
                    w1s[SD*SD/4 + idx] = m2[idx];
                }
            }
            const float4* wpg = (const float4*)(Wpre + (size_t)l*SD*ED);
            float4* wps = (float4*)(sh + SH_WPRE);
            for (int idx = tx; idx < SD*ED/4; idx += TPB) wps[idx] = wpg[idx];
        }

        gsync(++epoch * NCTA);   // publishes cj/vn/pn/p(l) + f(l-1)

        // ---- stage DYNAMICS only (post-gsync) ----
        {
            const float4* cjg = (const float4*)(g_cj + cbase*SD);
            float4* cjs = (float4*)(sh + SH_CJ);
            for (int idx = tx; idx < 64*SD/4; idx += TPB) cjs[idx] = cjg[idx];
            if (l > 0) {
                const float4* vg = (const float4*)(g_vn + cbase*48);
                float4* vs = (float4*)(sh + SH_V);
                for (int idx = tx; idx < 64*48/4; idx += TPB) vs[idx] = vg[idx];
                const float4* fg = (const float4*)(g_f + cbase*ED);
                float4* fs = (float4*)(sh + SH_F);
                for (int idx = tx; idx < 64*ED/4; idx += TPB) fs[idx] = fg[idx];
            }
            for (int idx = tx; idx < 192; idx += TPB) {
                sh[SH_P + idx]  = g_p[pin][cbase*3 + idx];
                sh[SH_PN + idx] = g_pn[cbase*3 + idx];
            }
        }
        __syncthreads();

        // ---- pair phase with FUSED edge(l-1) update, flat items ----
        {
            float* hb = sh + SH_HW + widx*64;
            const float b2g = sh[SH_TB + 32];
            const int eidx = lane & 15;
            const float bpv = (l > 0) ? bpost[(l-1)*ED + eidx] : 0.0f;
            const float4* Ta4 = (const float4*)(sh + SH_W1TT + lane*20);
            const float4* Tb4 = (const float4*)(sh + SH_W1TT + (lane+32)*20);
            const float*  Ta  = sh + SH_W1TT + lane*20;
            const float*  Tb  = sh + SH_W1TT + (lane+32)*20;
            const float4* wc4 = (const float4*)(sh + SH_W2T2 + lane*68);

            for (int k = widx; k < nit; k += 16) {
                int item = shi[SH_IT + k];
                int ig2 = item >> 6, j = item & 63;
                int lio = shi[SH_LI + ig2];

                // --- fused edge update for layer l-1 (item-private E row) ---
                if (l > 0) {
                    float x = sh[SH_F + lio*ED + eidx] + sh[SH_F + j*ED + eidx];
                    float tv = sh[SH_EI + k*ED + eidx] + silu(x);
                    if (lane < 16) hb[eidx] = tv;
                    __syncwarp();
                    float4 T0 = ((const float4*)hb)[0];
                    float4 T1 = ((const float4*)hb)[1];
                    float4 T2 = ((const float4*)hb)[2];
                    float4 T3 = ((const float4*)hb)[3];
                    const float* wq = sh + SH_WPS;
                    float o = bpv
                        + T0.x*wq[0*16+eidx]  + T0.y*wq[1*16+eidx]
                        + T0.z*wq[2*16+eidx]  + T0.w*wq[3*16+eidx]
                        + T1.x*wq[4*16+eidx]  + T1.y*wq[5*16+eidx]
                        + T1.z*wq[6*16+eidx]  + T1.w*wq[7*16+eidx]
                        + T2.x*wq[8*16+eidx]  + T2.y*wq[9*16+eidx]
                        + T2.z*wq[10*16+eidx] + T2.w*wq[11*16+eidx]
                        + T3.x*wq[12*16+eidx] + T3.y*wq[13*16+eidx]
                        + T3.z*wq[14*16+eidx] + T3.w*wq[15*16+eidx];
                    __syncwarp();
                    if (lane < 16) sh[SH_EI + k*ED + eidx] = o;
                    __syncwarp();
                }

                float pix = sh[SH_P + lio*3], piy = sh[SH_P + lio*3+1], piz = sh[SH_P + lio*3+2];
                float dx = sh[SH_P + j*3]-pix, dy = sh[SH_P + j*3+1]-piy, dz = sh[SH_P + j*3+2]-piz;
                float dd = sqrtf(fmaxf(dx*dx + dy*dy + dz*dz, 1e-6f));
                float ac = sh[SH_PN + lio*3]*sh[SH_PN + j*3]
                         + sh[SH_PN + lio*3+1]*sh[SH_PN + j*3+1]
                         + sh[SH_PN + lio*3+2]*sh[SH_PN + j*3+2];
                float env = 0.5f*(__cosf(dd*0.62831853f) + 1.0f);
                float ri = 1.0f/(1.0f + dd);
                float rnx = dx*ri, rny = dy*ri, rnz = dz*ri;

                const float4* Ep = (const float4*)(sh + SH_EI + k*ED);
                float4 E0 = Ep[0], E1 = Ep[1], E2 = Ep[2], E3 = Ep[3];

                float hvA = sh[SH_CI + ig2*64 + lane]      + sh[SH_CJ + j*SD + lane];
                float hvB = sh[SH_CI + ig2*64 + 32 + lane] + sh[SH_CJ + j*SD + 32 + lane];
                {
                    float4 w0 = Ta4[0], w1 = Ta4[1], w2 = Ta4[2], w3 = Ta4[3];
                    hvA += dd*w0.x + ac*w0.y + E0.x*w0.z + E0.y*w0.w
                         + E0.z*w1.x + E0.w*w1.y + E1.x*w1.z + E1.y*w1.w
                         + E1.z*w2.x + E1.w*w2.y + E2.x*w2.z + E2.y*w2.w
                         + E2.z*w3.x + E2.w*w3.y + E3.x*w3.z + E3.y*w3.w
                         + E3.z*Ta[16] + E3.w*Ta[17];
                }
                {
                    float4 w0 = Tb4[0], w1 = Tb4[1], w2 = Tb4[2], w3 = Tb4[3];
                    hvB += dd*w0.x + ac*w0.y + E0.x*w0.z + E0.y*w0.w
                         + E0.z*w1.x + E0.w*w1.y + E1.x*w1.z + E1.y*w1.w
                         + E1.z*w2.x + E1.w*w2.y + E2.x*w2.z + E2.y*w2.w
                         + E2.z*w3.x + E2.w*w3.y + E3.x*w3.z + E3.y*w3.w
                         + E3.z*Tb[16] + E3.w*Tb[17];
                }
                float hpA = silu(hvA)*env;
                float hpB = silu(hvB)*env;

                float gcp = hpA*sh[SH_W2T2 + 32*68 + lane] + hpB*sh[SH_W2T2 + 32*68 + 32 + lane];
                #pragma unroll
                for (int o = 16; o; o >>= 1) gcp += __shfl_xor_sync(0xffffffffu, gcp, o);
                float gc = gcp + b2g*env;

                hb[lane] = hpA; hb[32 + lane] = hpB;
                __syncwarp();
                const float4* h4 = (const float4*)hb;
                float a0=0,a1=0,a2=0,a3=0;
                #pragma unroll
                for (int q = 0; q < 16; q++) {
                    float4 h = h4[q];
                    float4 w = wc4[q];
                    a0 += h.x*w.x; a1 += h.y*w.y;
                    a2 += h.z*w.z; a3 += h.w*w.w;
                }
                float tailv = (a0+a1)+(a2+a3) + sh[SH_TB + lane]*env;
                __syncwarp();

                int d = lane & 15;
                float gr = __shfl_sync(0xffffffffu, tailv, d);
                float gv = __shfl_sync(0xffffffffu, tailv, 16 + d);
                float rnA = (lane < 16) ? rnx : rny;
                float vA = rnA*gr;
                float vB = rnz*gr;
                if (l > 0) {
                    vA += sh[SH_V + j*48 + lane]*gv;
                    if (lane < 16) vB += sh[SH_V + j*48 + 32 + lane]*gv;
                }
                float* rec = sh + SH_REC + k*RS;
                rec[lane]      = hpA;
                rec[32 + lane] = hpB;
                rec[64 + lane] = vA;
                if (lane < 16) rec[96 + lane] = vB;
                if (lane < 3)  rec[112 + lane] = gc * ((lane==0)?rnx:((lane==1)?rny:rnz));
                if (lane == 0) rec[115] = env;
            }
        }
        __syncthreads();

        // ---- owner reduction across all 128 threads ----
        {
            int o0 = shi[SH_OFF + grp], o1 = shi[SH_OFF + grp + 1];
            float a0 = 0.0f, a1 = 0.0f;
            if (t128 < 116) {
                int k = o0;
                for (; k + 1 < o1; k += 2) {
                    a0 += sh[SH_REC + k*RS + t128];
                    a1 += sh[SH_REC + (k+1)*RS + t128];
                }
                if (k < o1) a0 += sh[SH_REC + k*RS + t128];
            }
            float acc = a0 + a1;
            if (lower) shHb[t] = acc;                                // henv
            else if (t128 < 116) sh[SH_AB + grp*52 + (t128-64)] = acc;
            bar128(grp);
            if (lower) {
                float envs = sh[SH_AB + grp*52 + 51];
                const float4* hs = (const float4*)shHb;
                const float4* wc = (const float4*)(sh + SH_W2T + t*68);
                float b0=0,b1v=0,b2v=0,b3=0;
                #pragma unroll
                for (int q = 0; q < 16; q++) {
                    float4 h4 = hs[q];
                    float4 w4 = wc[q];
                    b0 += h4.x*w4.x; b1v += h4.y*w4.y;
                    b2v += h4.z*w4.z; b3 += h4.w*w4.w;
                }
                s_reg += (b0+b1v)+(b2v+b3) + b2[l*DOUT + t]*envs;
                float accb = (t < 51) ? sh[SH_AB + grp*52 + t] : 0.0f;
                if (t < 48) v_reg += accb * dinv;
                if (t >= 48 && t < 51)
                    g_p[pout][i*3 + (t-48)] = sh[SH_P + li*3 + (t-48)] + accb * dinv;
            }
            bar128(grp);
        }

        // ---- node_post (lower 64 only) ----
        if (lower) {
            if (l < LL-1) {
                shHb[t] = s_reg;
                bar64(grp);
                const float* wm1 = sh + SH_W1S;
                float m0 = bm1[l*SD + t], m1 = 0.0f;
                #pragma unroll 8
                for (int kk = 0; kk < SD; kk += 2) {
                    m0 += shHb[kk]   * wm1[kk*SD + t];
                    m1 += shHb[kk+1] * wm1[(kk+1)*SD + t];
                }
                float hm = silu(m0 + m1);
                shHb[68 + t] = hm;
                bar64(grp);
                const float* wm2 = sh + SH_W1S + SD*SD;
                float q0 = bm2[l*SD + t], q1 = 0.0f;
                #pragma unroll 8
                for (int kk = 0; kk < SD; kk += 2) {
                    q0 += shHb[68+kk]   * wm2[kk*SD + t];
                    q1 += shHb[68+kk+1] * wm2[(kk+1)*SD + t];
                }
                s_reg += q0 + q1;
                bar64(grp);
            }
            shHb[t] = s_reg;
            bar64(grp);
            if (t < ED) {
                const float* wp = sh + SH_WPRE;
                float f0 = bpre[l*ED + t], f1 = 0.0f;
                #pragma unroll 8
                for (int kk = 0; kk < SD; kk += 2) {
                    f0 += shHb[kk]   * wp[kk*ED + t];
                    f1 += shHb[kk+1] * wp[(kk+1)*ED + t];
                }
                g_f[i*ED + t] = f0 + f1;
            }
        }
    }

    gsync(++epoch * NCTA);   // publish f(LL-1)

    // ---- final edge update ----
    {
        const float4* fg = (const float4*)(g_f + cbase*ED);
        float4* fs = (float4*)(sh + SH_F);
        for (int idx = tx; idx < 64*ED/4; idx += TPB) fs[idx] = fg[idx];
        for (int idx = tx; idx < ED*ED; idx += TPB)
            sh[SH_WPS + idx] = Wpost[(LL-1)*ED*ED + idx];
    }
    __syncthreads();
    {
        int hw = lane >> 4, e = lane & 15;
        float bp = bpost[(LL-1)*ED + e];
        for (int b = widx*2; b < nit; b += 32) {
            int k = b + hw;
            bool act = (k < nit);
            int sl = act ? k : 0;
            int item = shi[SH_IT + sl];
            int ig2 = item >> 6, j = item & 63;
            float x = sh[SH_F + shi[SH_LI + ig2]*ED + e] + sh[SH_F + j*ED + e];
            float tv = sh[SH_EI + sl*ED + e] + silu(x);
            float o = bp;
            #pragma unroll
            for (int m = 0; m < ED; m++) {
                float tm = __shfl_sync(0xffffffffu, tv, (hw << 4) + m);
                o += tm * sh[SH_WPS + m*ED + e];
            }
            if (act) sh[SH_EI + sl*ED + e] = o;
        }
    }
    __syncthreads();

    // -------- output --------
    if (lower) {
        out[i*SD + t] = s_reg;
        if (t < 48) out[OFF_V + i*48 + t] = v_reg;
        if (t < 3)  out[OFF_P + i*3 + t] = g_p[LL & 1][i*3 + t];
    }
    for (int idx = tx; idx < nit*ED; idx += TPB) {
        int item = shi[SH_IT + (idx >> 4)];
        int c = idx & 15;
        int ig2 = item >> 6, j = item & 63;
        int lio = shi[SH_LI + ig2];
        int e = gg*EPG + lio*63 + j - (j > lio ? 1 : 0);
        out[OFF_E + (size_t)e*ED + c] = sh[SH_EI + idx];
    }
    {
        const int e0 = blockIdx.x * (8*EPG / NCTA);
        for (int q = tx; q < (8*EPG/NCTA)*ED; q += TPB) {
            int e = e0 + (q >> 4), c = q & 15;
            int gg2 = e / EPG, rem = e - gg2*EPG;
            int si = rem / 63, t63 = rem - si*63;
            int ti = t63 + (t63 >= si ? 1 : 0);
            int a = gg2*64 + si, b = gg2*64 + ti;
            float dx = p_in[a*3]   - p_in[b*3];
            float dy = p_in[a*3+1] - p_in[b*3+1];
            float dz = p_in[a*3+2] - p_in[b*3+2];
            if (!(dx*dx + dy*dy + dz*dz < 25.0f))
                out[OFF_E + (size_t)e*ED + c] = ea[(size_t)e*ED + c];
        }
    }
}

// ---------------- launch ----------------
extern "C" void kernel_launch(void* const* d_in, const int* in_sizes, int n_in,
                              void* d_out, int out_size) {
    const float* s    = (const float*)d_in[0];
    const float* v    = (const float*)d_in[1];
    const float* p    = (const float*)d_in[2];
    const float* ea   = (const float*)d_in[3];
    const float* ln_g = (const float*)d_in[6];
    const float* ln_b = (const float*)d_in[7];
    const float* W1   = (const float*)d_in[8];
    const float* b1   = (const float*)d_in[9];
    const float* W2   = (const float*)d_in[10];
    const float* b2   = (const float*)d_in[11];
    const float* Wm1  = (const float*)d_in[12];
    const float* bm1  = (const float*)d_in[13];
    const float* Wm2  = (const float*)d_in[14];
    const float* bm2  = (const float*)d_in[15];
    const float* Wpre = (const float*)d_in[16];
    const float* bpre = (const float*)d_in[17];
    const float* Wpost= (const float*)d_in[18];
    const float* bpost= (const float*)d_in[19];
    float* out = (float*)d_out;

    cudaFuncSetAttribute(k_fused, cudaFuncAttributeMaxDynamicSharedMemorySize, SMEM_BYTES);
    k_init<<<1, NN>>>(p);
    k_fused<<<NCTA, TPB, SMEM_BYTES>>>(s, v, p, ea, ln_g, ln_b, W1, b1, W2, b2,
                                       Wm1, bm1, Wm2, bm2, Wpre, bpre, Wpost, bpost, out);
}

// round 14
// speedup vs baseline: 1.0119x; 1.0108x over previous
#include <cuda_runtime.h>
#include <math.h>

#define NN 512
#define SD 64
#define ED 16
#define LL 5
#define DOUT 97
#define EPG 4032
#define NCTA 128
#define TPB 512
#define RS 116

#define OFF_V (NN*SD)
#define OFF_E (OFF_V + NN*48)
#define OFF_P (OFF_E + 8*EPG*ED)

// ---- shared layout (float offsets) ----
#define SH_W2T   0        /* 64*68 */
#define SH_W2T2  4352     /* 33*68 */
#define SH_W1TT  6596     /* 64*20 : W1 tail per-col transposed */
#define SH_WPS   7876     /* 256 */
#define SH_W1S   8132     /* 8192 : W1 rows 0..127 (reused Wm1|Wm2 pre-gsync) */
#define SH_CJ    16324    /* 4096 */
#define SH_CI    20420    /* 256 */
#define SH_V     20676    /* 3072 */
#define SH_P     23748    /* 192 */
#define SH_PN    23940    /* 192 */
#define SH_F     24132    /* 1024 */
#define SH_TB    25156    /* 40 */
#define SH_H     25196    /* 4*140 */
#define SH_RED   25756    /* 32 */
#define SH_AB    25788    /* 4*52 */
#define SH_HW    25996    /* 16*64 */
#define SH_EI    27020    /* 4096 */
#define SH_REC   31116    /* 160*116 */
#define SH_IT    49676    /* 256 ints */
#define SH_NBR   49932    /* 256 ints */
#define SH_OFF   50188    /* 8 ints */
#define SH_CNT   50196    /* 4 ints */
#define SH_LI    50200    /* 4 ints */
#define SH_WCNT  50204    /* 8 ints */
#define SH_WPRE  50212    /* 1024 : Wpre own buffer */
#define SH_TOTAL 51236
#define SMEM_BYTES (SH_TOTAL*4)

// ---------------- device state ----------------
__device__ float g_cj[NN*SD];
__device__ float g_vn[NN*48];
__device__ float g_p[2][NN*3];
__device__ float g_pn[NN*3];
__device__ float g_f[NN*ED];
__device__ int   g_map[NN];
__device__ unsigned int g_ctrs[8*32];   // one counter per molecular group, 128B apart

__device__ __forceinline__ void bar64(int grp) {
    asm volatile("bar.sync %0, 64;" :: "r"(grp + 1) : "memory");
}
__device__ __forceinline__ void bar128(int grp) {
    asm volatile("bar.sync %0, 128;" :: "r"(grp + 5) : "memory");
}
__device__ __forceinline__ float silu(float x) {
    return x * (1.0f / (1.0f + __expf(-x)));
}
// per-molecular-group barrier: 16 CTAs arrive; target = epoch*16
__device__ __forceinline__ void gsync_g(int gg, unsigned int target) {
    __syncthreads();
    __threadfence();
    if (threadIdx.x == 0) {
        atomicAdd(&g_ctrs[gg*32], 1u);
        volatile unsigned int* c = &g_ctrs[gg*32];
        while (*c < target) { }
        __threadfence();
    }
    __syncthreads();
}

// ---------------- init: degree-balanced node->CTA map ----------------
__global__ void k_init(const float* __restrict__ p) {
    __shared__ int cnt_s[NN];
    int n = threadIdx.x;
    int gb = (n >> 6) << 6;
    float px = p[n*3], py = p[n*3+1], pz = p[n*3+2];
    int cnt = 0;
    for (int j = 0; j < 64; j++) {
        int jg = gb + j;
        if (jg == n) continue;
        float dx = p[jg*3]-px, dy = p[jg*3+1]-py, dz = p[jg*3+2]-pz;
        if (dx*dx + dy*dy + dz*dz < 25.0f) cnt++;
    }
    cnt_s[n] = cnt;
    __syncthreads();
    int rank = 0;
    for (int j = 0; j < 64; j++) {
        int cj = cnt_s[gb + j];
        if (cj > cnt || (cj == cnt && (gb + j) < n)) rank++;
    }
    int round = rank >> 4, pos = rank & 15;
    int cta = (round & 1) ? (15 - pos) : pos;
    g_map[(((n >> 6)*16 + cta) << 2) + round] = n;
    g_p[0][n*3] = px; g_p[0][n*3+1] = py; g_p[0][n*3+2] = pz;
    if (n < 8) g_ctrs[n*32] = 0u;
}

__global__ void __launch_bounds__(TPB, 1)
k_fused(const float* __restrict__ s_in, const float* __restrict__ v_in,
        const float* __restrict__ p_in, const float* __restrict__ ea,
        const float* __restrict__ ln_g, const float* __restrict__ ln_b,
        const float* __restrict__ W1,  const float* __restrict__ b1,
        const float* __restrict__ W2,  const float* __restrict__ b2,
        const float* __restrict__ Wm1, const float* __restrict__ bm1,
        const float* __restrict__ Wm2, const float* __restrict__ bm2,
        const float* __restrict__ Wpre,const float* __restrict__ bpre,
        const float* __restrict__ Wpost,const float* __restrict__ bpost,
        float* __restrict__ out)
{
    extern __shared__ float sh[];
    int* shi = (int*)sh;
    const int tx   = threadIdx.x;
    const int grp  = tx >> 7;
    const int t128 = tx & 127;
    const int t    = tx & 63;
    const int lane = tx & 31;
    const int widx = tx >> 5;
    const bool lower = (t128 < 64);
    const int wrp  = t >> 5;
    const int gg   = blockIdx.x >> 4;
    const int cbase = gg << 6;
    const int i    = g_map[blockIdx.x*4 + grp];
    const int li   = i & 63;
    unsigned int epoch = 0;
    float* shHb = sh + SH_H + grp*140;

    float s_reg = s_in[i*SD + t];
    float v_reg = (t < 48) ? v_in[i*48 + t] : 0.0f;

    // -------- adjacency (lower 64 per node) --------
    if (lower) {
        float pix = p_in[i*3], piy = p_in[i*3+1], piz = p_in[i*3+2];
        int jg = cbase + t;
        float dx = p_in[jg*3]-pix, dy = p_in[jg*3+1]-piy, dz = p_in[jg*3+2]-piz;
        bool ok = (jg != i) && (dx*dx + dy*dy + dz*dz < 25.0f);
        unsigned m = __ballot_sync(0xffffffffu, ok);
        if (lane == 0) shi[SH_WCNT + grp*2 + wrp] = __popc(m);
        bar64(grp);
        int base = (wrp == 1) ? shi[SH_WCNT + grp*2] : 0;
        if (ok) shi[SH_NBR + grp*64 + base + __popc(m & ((1u << lane) - 1u))] = t;
        if (t == 0) {
            shi[SH_CNT + grp] = shi[SH_WCNT + grp*2] + shi[SH_WCNT + grp*2 + 1];
            shi[SH_LI + grp] = li;
        }
        bar64(grp);
    }
    __syncthreads();
    if (tx == 0) {
        int o = 0; shi[SH_OFF] = 0;
        #pragma unroll
        for (int n = 0; n < 4; n++) { o += shi[SH_CNT + n]; shi[SH_OFF + n + 1] = o; }
    }
    __syncthreads();
    const int cnt = shi[SH_CNT + grp];
    const float dinv = 1.0f / fmaxf((float)cnt, 1.0f);
    if (lower && t < cnt)
        shi[SH_IT + shi[SH_OFF + grp] + t] = (grp << 6) | shi[SH_NBR + grp*64 + t];
    __syncthreads();
    const int nit = shi[SH_OFF + 4];

    // E slice into smem
    for (int idx = tx; idx < nit*ED; idx += TPB) {
        int item = shi[SH_IT + (idx >> 4)];
        int c = idx & 15;
        int ig2 = item >> 6, j = item & 63;
        int lio = shi[SH_LI + ig2];
        int e = gg*EPG + lio*63 + j - (j > lio ? 1 : 0);
        sh[SH_EI + idx] = ea[(size_t)e*ED + c];
    }

    // -------- layers --------
    for (int l = 0; l < LL; l++) {
        const int pin = l & 1, pout = pin ^ 1;

        __syncthreads();
        {
            const float4* w1g = (const float4*)(W1 + (size_t)l*146*SD);
            float4* w1s = (float4*)(sh + SH_W1S);
            for (int idx = tx; idx < 128*SD/4; idx += TPB) w1s[idx] = w1g[idx];
        }
        __syncthreads();

        // ---- node_pre ----
        if (lower) {
            float xs = s_reg, xq = s_reg*s_reg;
            float xv = (t < 48) ? v_reg*v_reg : 0.0f;
            #pragma unroll
            for (int o = 16; o; o >>= 1) {
                xs += __shfl_down_sync(0xffffffffu, xs, o);
                xq += __shfl_down_sync(0xffffffffu, xq, o);
                xv += __shfl_down_sync(0xffffffffu, xv, o);
            }
            bar64(grp);
            if (lane == 0) {
                float* r = sh + SH_RED + grp*8 + wrp*3;
                r[0] = xs; r[1] = xq; r[2] = xv;
            }
            bar64(grp);
            const float* r = sh + SH_RED + grp*8;
            float mu   = (r[0] + r[3]) * (1.0f/64);
            float var  = (r[1] + r[4]) * (1.0f/64) - mu*mu;
            float vinv = rsqrtf((r[2] + r[5]) * (1.0f/16) + 1e-6f);
            s_reg = (s_reg - mu) * rsqrtf(fmaxf(var, 0.0f) + 1e-6f) * ln_g[l*SD + t] + ln_b[l*SD + t];
            shHb[t] = s_reg;
            if (t < 48) { v_reg *= vinv; g_vn[i*48 + t] = v_reg; }
            if (t < 3) {
                float p0 = g_p[pin][i*3], p1 = g_p[pin][i*3+1], p2 = g_p[pin][i*3+2];
                float inv = rsqrtf(p0*p0 + p1*p1 + p2*p2);
                g_pn[i*3 + t] = g_p[pin][i*3 + t] * inv;
            }
        }
        bar128(grp);
        {
            int which = t128 >> 6;
            const float* w1s = sh + SH_W1S + which*4096;
            float a0 = which ? 0.0f : b1[l*SD + t];
            float a1 = 0.0f;
            #pragma unroll 8
            for (int k = 0; k < SD; k += 2) {
                a0 += shHb[k]   * w1s[k*64 + t];
                a1 += shHb[k+1] * w1s[(k+1)*64 + t];
            }
            float acc = a0 + a1;
            if (which == 0) sh[SH_CI + grp*64 + t] = acc;
            else            g_cj[i*SD + t] = acc;
        }

        // ---- stage ALL WEIGHTS pre-gsync (overlaps barrier wait) ----
        __syncthreads();
        {
            const float* w2g = W2 + (size_t)l*SD*DOUT;
            for (int idx = tx; idx < SD*DOUT; idx += TPB) {
                int kk = idx / DOUT, col = idx - kk*DOUT;
                float w = w2g[idx];
                if (col < 64) sh[SH_W2T + col*68 + kk] = w;
                else          sh[SH_W2T2 + (col-64)*68 + kk] = w;
            }
            for (int idx = tx; idx < 64*18; idx += TPB) {
                int col = idx / 18, row = idx - col*18;
                sh[SH_W1TT + col*20 + row] = W1[(size_t)l*146*SD + (128+row)*SD + col];
            }
            for (int idx = tx; idx < 33; idx += TPB)
                sh[SH_TB + idx] = b2[l*DOUT + 64 + idx];
            if (l > 0) {
                for (int idx = tx; idx < ED*ED; idx += TPB)
                    sh[SH_WPS + idx] = Wpost[(l-1)*ED*ED + idx];
            }
            if (l < LL-1) {
                const float4* m1 = (const float4*)(Wm1 + (size_t)l*SD*SD);
                const float4* m2 = (const float4*)(Wm2 + (size_t)l*SD*SD);
                float4* w1s = (float4*)(sh + SH_W1S);
                for (int idx = tx; idx < SD*SD/4; idx += TPB) {
                    w1s[idx] = m1[idx];
                    w1s[SD*SD/4 + idx] = m2[idx];
                }
            }
            const float4* wpg = (const float4*)(Wpre + (size_t)l*SD*ED);
            float4* wps = (float4*)(sh + SH_WPRE);
            for (int idx = tx; idx < SD*ED/4; idx += TPB) wps[idx] = wpg[idx];
        }

        gsync_g(gg, ++epoch * 16);   // group-local: cj/vn/pn/p(l) + f(l-1)

        // ---- stage DYNAMICS only (post-gsync) ----
        {
            const float4* cjg = (const float4*)(g_cj + cbase*SD);
            float4* cjs = (float4*)(sh + SH_CJ);
            for (int idx = tx; idx < 64*SD/4; idx += TPB) cjs[idx] = cjg[idx];
            if (l > 0) {
                const float4* vg = (const float4*)(g_vn + cbase*48);
                float4* vs = (float4*)(sh + SH_V);
                for (int idx = tx; idx < 64*48/4; idx += TPB) vs[idx] = vg[idx];
                const float4* fg = (const float4*)(g_f + cbase*ED);
                float4* fs = (float4*)(sh + SH_F);
                for (int idx = tx; idx < 64*ED/4; idx += TPB) fs[idx] = fg[idx];
            }
            for (int idx = tx; idx < 192; idx += TPB) {
                sh[SH_P + idx]  = g_p[pin][cbase*3 + idx];
                sh[SH_PN + idx] = g_pn[cbase*3 + idx];
            }
        }
        __syncthreads();

        // ---- pair phase with FUSED edge(l-1) update, flat items ----
        {
            float* hb = sh + SH_HW + widx*64;
            const float b2g = sh[SH_TB + 32];
            const int eidx = lane & 15;
            const float bpv = (l > 0) ? bpost[(l-1)*ED + eidx] : 0.0f;
            const float4* Ta4 = (const float4*)(sh + SH_W1TT + lane*20);
            const float4* Tb4 = (const float4*)(sh + SH_W1TT + (lane+32)*20);
            const float*  Ta  = sh + SH_W1TT + lane*20;
            const float*  Tb  = sh + SH_W1TT + (lane+32)*20;
            const float4* wc4 = (const float4*)(sh + SH_W2T2 + lane*68);

            for (int k = widx; k < nit; k += 16) {
                int item = shi[SH_IT + k];
                int ig2 = item >> 6, j = item & 63;
                int lio = shi[SH_LI + ig2];

                // --- fused edge update for layer l-1 (item-private E row) ---
                if (l > 0) {
                    float x = sh[SH_F + lio*ED + eidx] + sh[SH_F + j*ED + eidx];
                    float tv = sh[SH_EI + k*ED + eidx] + silu(x);
                    if (lane < 16) hb[eidx] = tv;
                    __syncwarp();
                    float4 T0 = ((const float4*)hb)[0];
                    float4 T1 = ((const float4*)hb)[1];
                    float4 T2 = ((const float4*)hb)[2];
                    float4 T3 = ((const float4*)hb)[3];
                    const float* wq = sh + SH_WPS;
                    float o = bpv
                        + T0.x*wq[0*16+eidx]  + T0.y*wq[1*16+eidx]
                        + T0.z*wq[2*16+eidx]  + T0.w*wq[3*16+eidx]
                        + T1.x*wq[4*16+eidx]  + T1.y*wq[5*16+eidx]
                        + T1.z*wq[6*16+eidx]  + T1.w*wq[7*16+eidx]
                        + T2.x*wq[8*16+eidx]  + T2.y*wq[9*16+eidx]
                        + T2.z*wq[10*16+eidx] + T2.w*wq[11*16+eidx]
                        + T3.x*wq[12*16+eidx] + T3.y*wq[13*16+eidx]
                        + T3.z*wq[14*16+eidx] + T3.w*wq[15*16+eidx];
                    __syncwarp();
                    if (lane < 16) sh[SH_EI + k*ED + eidx] = o;
                    __syncwarp();
                }

                float pix = sh[SH_P + lio*3], piy = sh[SH_P + lio*3+1], piz = sh[SH_P + lio*3+2];
                float dx = sh[SH_P + j*3]-pix, dy = sh[SH_P + j*3+1]-piy, dz = sh[SH_P + j*3+2]-piz;
                float dd = sqrtf(fmaxf(dx*dx + dy*dy + dz*dz, 1e-6f));
                float ac = sh[SH_PN + lio*3]*sh[SH_PN + j*3]
                         + sh[SH_PN + lio*3+1]*sh[SH_PN + j*3+1]
                         + sh[SH_PN + lio*3+2]*sh[SH_PN + j*3+2];
                float env = 0.5f*(__cosf(dd*0.62831853f) + 1.0f);
                float ri = 1.0f/(1.0f + dd);
                float rnx = dx*ri, rny = dy*ri, rnz = dz*ri;

                const float4* Ep = (const float4*)(sh + SH_EI + k*ED);
                float4 E0 = Ep[0], E1 = Ep[1], E2 = Ep[2], E3 = Ep[3];

                float hvA = sh[SH_CI + ig2*64 + lane]      + sh[SH_CJ + j*SD + lane];
                float hvB = sh[SH_CI + ig2*64 + 32 + lane] + sh[SH_CJ + j*SD + 32 + lane];
                {
                    float4 w0 = Ta4[0], w1 = Ta4[1], w2 = Ta4[2], w3 = Ta4[3];
                    hvA += dd*w0.x + ac*w0.y + E0.x*w0.z + E0.y*w0.w
                         + E0.z*w1.x + E0.w*w1.y + E1.x*w1.z + E1.y*w1.w
                         + E1.z*w2.x + E1.w*w2.y + E2.x*w2.z + E2.y*w2.w
                         + E2.z*w3.x + E2.w*w3.y + E3.x*w3.z + E3.y*w3.w
                         + E3.z*Ta[16] + E3.w*Ta[17];
                }
                {
                    float4 w0 = Tb4[0], w1 = Tb4[1], w2 = Tb4[2], w3 = Tb4[3];
                    hvB += dd*w0.x + ac*w0.y + E0.x*w0.z + E0.y*w0.w
                         + E0.z*w1.x + E0.w*w1.y + E1.x*w1.z + E1.y*w1.w
                         + E1.z*w2.x + E1.w*w2.y + E2.x*w2.z + E2.y*w2.w
                         + E2.z*w3.x + E2.w*w3.y + E3.x*w3.z + E3.y*w3.w
                         + E3.z*Tb[16] + E3.w*Tb[17];
                }
                float hpA = silu(hvA)*env;
                float hpB = silu(hvB)*env;

                float gcp = hpA*sh[SH_W2T2 + 32*68 + lane] + hpB*sh[SH_W2T2 + 32*68 + 32 + lane];
                #pragma unroll
                for (int o = 16; o; o >>= 1) gcp += __shfl_xor_sync(0xffffffffu, gcp, o);
                float gc = gcp + b2g*env;

                hb[lane] = hpA; hb[32 + lane] = hpB;
                __syncwarp();
                const float4* h4 = (const float4*)hb;
                float a0=0,a1=0,a2=0,a3=0;
                #pragma unroll
                for (int q = 0; q < 16; q++) {
                    float4 h = h4[q];
                    float4 w = wc4[q];
                    a0 += h.x*w.x; a1 += h.y*w.y;
                    a2 += h.z*w.z; a3 += h.w*w.w;
                }
                float tailv = (a0+a1)+(a2+a3) + sh[SH_TB + lane]*env;
                __syncwarp();

                int d = lane & 15;
                float gr = __shfl_sync(0xffffffffu, tailv, d);
                float gv = __shfl_sync(0xffffffffu, tailv, 16 + d);
                float rnA = (lane < 16) ? rnx : rny;
                float vA = rnA*gr;
                float vB = rnz*gr;
                if (l > 0) {
                    vA += sh[SH_V + j*48 + lane]*gv;
                    if (lane < 16) vB += sh[SH_V + j*48 + 32 + lane]*gv;
                }
                float* rec = sh + SH_REC + k*RS;
                rec[lane]      = hpA;
                rec[32 + lane] = hpB;
                rec[64 + lane] = vA;
                if (lane < 16) rec[96 + lane] = vB;
                if (lane < 3)  rec[112 + lane] = gc * ((lane==0)?rnx:((lane==1)?rny:rnz));
                if (lane == 0) rec[115] = env;
            }
        }
        __syncthreads();

        // ---- owner reduction across all 128 threads ----
        {
            int o0 = shi[SH_OFF + grp], o1 = shi[SH_OFF + grp + 1];
            float a0 = 0.0f, a1 = 0.0f;
            if (t128 < 116) {
                int k = o0;
                for (; k + 1 < o1; k += 2) {
                    a0 += sh[SH_REC + k*RS + t128];
                    a1 += sh[SH_REC + (k+1)*RS + t128];
                }
                if (k < o1) a0 += sh[SH_REC + k*RS + t128];
            }
            float acc = a0 + a1;
            if (lower) shHb[t] = acc;                                // henv
            else if (t128 < 116) sh[SH_AB + grp*52 + (t128-64)] = acc;
            bar128(grp);
            if (lower) {
                float envs = sh[SH_AB + grp*52 + 51];
                const float4* hs = (const float4*)shHb;
                const float4* wc = (const float4*)(sh + SH_W2T + t*68);
                float b0=0,b1v=0,b2v=0,b3=0;
                #pragma unroll
                for (int q = 0; q < 16; q++) {
                    float4 h4 = hs[q];
                    float4 w4 = wc[q];
                    b0 += h4.x*w4.x; b1v += h4.y*w4.y;
                    b2v += h4.z*w4.z; b3 += h4.w*w4.w;
                }
                s_reg += (b0+b1v)+(b2v+b3) + b2[l*DOUT + t]*envs;
                float accb = (t < 51) ? sh[SH_AB + grp*52 + t] : 0.0f;
                if (t < 48) v_reg += accb * dinv;
                if (t >= 48 && t < 51)
                    g_p[pout][i*3 + (t-48)] = sh[SH_P + li*3 + (t-48)] + accb * dinv;
            }
            bar128(grp);
        }

        // ---- node_post (lower 64 only) ----
        if (lower) {
            if (l < LL-1) {
                shHb[t] = s_reg;
                bar64(grp);
                const float* wm1 = sh + SH_W1S;
                float m0 = bm1[l*SD + t], m1 = 0.0f;
                #pragma unroll 8
                for (int kk = 0; kk < SD; kk += 2) {
                    m0 += shHb[kk]   * wm1[kk*SD + t];
                    m1 += shHb[kk+1] * wm1[(kk+1)*SD + t];
                }
                float hm = silu(m0 + m1);
                shHb[68 + t] = hm;
                bar64(grp);
                const float* wm2 = sh + SH_W1S + SD*SD;
                float q0 = bm2[l*SD + t], q1 = 0.0f;
                #pragma unroll 8
                for (int kk = 0; kk < SD; kk += 2) {
                    q0 += shHb[68+kk]   * wm2[kk*SD + t];
                    q1 += shHb[68+kk+1] * wm2[(kk+1)*SD + t];
                }
                s_reg += q0 + q1;
                bar64(grp);
            }
            shHb[t] = s_reg;
            bar64(grp);
            if (t < ED) {
                const float* wp = sh + SH_WPRE;
                float f0 = bpre[l*ED + t], f1 = 0.0f;
                #pragma unroll 8
                for (int kk = 0; kk < SD; kk += 2) {
                    f0 += shHb[kk]   * wp[kk*ED + t];
                    f1 += shHb[kk+1] * wp[(kk+1)*ED + t];
                }
                g_f[i*ED + t] = f0 + f1;
            }
        }
    }

    gsync_g(gg, ++epoch * 16);   // group-local: publish f(LL-1)

    // ---- final edge update ----
    {
        const float4* fg = (const float4*)(g_f + cbase*ED);
        float4* fs = (float4*)(sh + SH_F);
        for (int idx = tx; idx < 64*ED/4; idx += TPB) fs[idx] = fg[idx];
        for (int idx = tx; idx < ED*ED; idx += TPB)
            sh[SH_WPS + idx] = Wpost[(LL-1)*ED*ED + idx];
    }
    __syncthreads();
    {
        int hw = lane >> 4, e = lane & 15;
        float bp = bpost[(LL-1)*ED + e];
        for (int b = widx*2; b < nit; b += 32) {
            int k = b + hw;
            bool act = (k < nit);
            int sl = act ? k : 0;
            int item = shi[SH_IT + sl];
            int ig2 = item >> 6, j = item & 63;
            float x = sh[SH_F + shi[SH_LI + ig2]*ED + e] + sh[SH_F + j*ED + e];
            float tv = sh[SH_EI + sl*ED + e] + silu(x);
            float o = bp;
            #pragma unroll
            for (int m = 0; m < ED; m++) {
                float tm = __shfl_sync(0xffffffffu, tv, (hw << 4) + m);
                o += tm * sh[SH_WPS + m*ED + e];
            }
            if (act) sh[SH_EI + sl*ED + e] = o;
        }
    }
    __syncthreads();

    // -------- output --------
    if (lower) {
        out[i*SD + t] = s_reg;
        if (t < 48) out[OFF_V + i*48 + t] = v_reg;
        if (t < 3)  out[OFF_P + i*3 + t] = g_p[LL & 1][i*3 + t];
    }
    for (int idx = tx; idx < nit*ED; idx += TPB) {
        int item = shi[SH_IT + (idx >> 4)];
        int c = idx & 15;
        int ig2 = item >> 6, j = item & 63;
        int lio = shi[SH_LI + ig2];
        int e = gg*EPG + lio*63 + j - (j > lio ? 1 : 0);
        out[OFF_E + (size_t)e*ED + c] = sh[SH_EI + idx];
    }
    {
        const int e0 = blockIdx.x * (8*EPG / NCTA);
        for (int q = tx; q < (8*EPG/NCTA)*ED; q += TPB) {
            int e = e0 + (q >> 4), c = q & 15;
            int gg2 = e / EPG, rem = e - gg2*EPG;
            int si = rem / 63, t63 = rem - si*63;
            int ti = t63 + (t63 >= si ? 1 : 0);
            int a = gg2*64 + si, b = gg2*64 + ti;
            float dx = p_in[a*3]   - p_in[b*3];
            float dy = p_in[a*3+1] - p_in[b*3+1];
            float dz = p_in[a*3+2] - p_in[b*3+2];
            if (!(dx*dx + dy*dy + dz*dz < 25.0f))
                out[OFF_E + (size_t)e*ED + c] = ea[(size_t)e*ED + c];
        }
    }
}

// ---------------- launch ----------------
extern "C" void kernel_launch(void* const* d_in, const int* in_sizes, int n_in,
                              void* d_out, int out_size) {
    const float* s    = (const float*)d_in[0];
    const float* v    = (const float*)d_in[1];
    const float* p    = (const float*)d_in[2];
    const float* ea   = (const float*)d_in[3];
    const float* ln_g = (const float*)d_in[6];
    const float* ln_b = (const float*)d_in[7];
    const float* W1   = (const float*)d_in[8];
    const float* b1   = (const float*)d_in[9];
    const float* W2   = (const float*)d_in[10];
    const float* b2   = (const float*)d_in[11];
    const float* Wm1  = (const float*)d_in[12];
    const float* bm1  = (const float*)d_in[13];
    const float* Wm2  = (const float*)d_in[14];
    const float* bm2  = (const float*)d_in[15];
    const float* Wpre = (const float*)d_in[16];
    const float* bpre = (const float*)d_in[17];
    const float* Wpost= (const float*)d_in[18];
    const float* bpost= (const float*)d_in[19];
    float* out = (float*)d_out;

    cudaFuncSetAttribute(k_fused, cudaFuncAttributeMaxDynamicSharedMemorySize, SMEM_BYTES);
    k_init<<<1, NN>>>(p);
    k_fused<<<NCTA, TPB, SMEM_BYTES>>>(s, v, p, ea, ln_g, ln_b, W1, b1, W2, b2,
                                       Wm1, bm1, Wm2, bm2, Wpre, bpre, Wpost, bpost, out);
}

// round 15
// speedup vs baseline: 1.0459x; 1.0336x over previous
#include <cuda_runtime.h>
#include <math.h>

#define NN 512
#define SD 64
#define ED 16
#define LL 5
#define DOUT 97
#define EPG 4032
#define NCTA 128
#define TPB 512
#define RS 116

#define OFF_V (NN*SD)
#define OFF_E (OFF_V + NN*48)
#define OFF_P (OFF_E + 8*EPG*ED)

// ---- shared layout (float offsets) ----
#define SH_W2T   0        /* 64*68 */
#define SH_W2T2  4352     /* 33*68 */
#define SH_W1TT  6596     /* 64*20 : W1 tail per-col transposed */
#define SH_WPS   7876     /* 256 */
#define SH_W1S   8132     /* 8192 : Wm1|Wm2 (staged pre-gsync) */
#define SH_CJ    16324    /* 4096 */
#define SH_CI    20420    /* 256 */
#define SH_V     20676    /* 3072 */
#define SH_P     23748    /* 192 */
#define SH_PN    23940    /* 192 */
#define SH_F     24132    /* 1024 */
#define SH_TB    25156    /* 40 */
#define SH_H     25196    /* 4*140 */
#define SH_RED   25756    /* 32 */
#define SH_AB    25788    /* 4*52 */
#define SH_HW    25996    /* 16*64 */
#define SH_EI    27020    /* 4096 */
#define SH_REC   31116    /* 160*116 */
#define SH_IT    49676    /* 256 ints */
#define SH_NBR   49932    /* 256 ints */
#define SH_OFF   50188    /* 8 ints */
#define SH_CNT   50196    /* 4 ints */
#define SH_LI    50200    /* 4 ints */
#define SH_WCNT  50204    /* 8 ints */
#define SH_WPRE  50212    /* 1024 : Wpre own buffer */
#define SH_TOTAL 51236
#define SMEM_BYTES (SH_TOTAL*4)

// ---------------- device state ----------------
__device__ float g_cj[NN*SD];
__device__ float g_vn[NN*48];
__device__ float g_p[2][NN*3];
__device__ float g_pn[NN*3];
__device__ float g_f[NN*ED];
__device__ int   g_map[NN];
__device__ unsigned int g_ctrs[8*32];   // one counter per molecular group, 128B apart

__device__ __forceinline__ void bar64(int grp) {
    asm volatile("bar.sync %0, 64;" :: "r"(grp + 1) : "memory");
}
__device__ __forceinline__ void bar128(int grp) {
    asm volatile("bar.sync %0, 128;" :: "r"(grp + 5) : "memory");
}
__device__ __forceinline__ float silu(float x) {
    return x * (1.0f / (1.0f + __expf(-x)));
}
// per-molecular-group barrier: 16 CTAs arrive; target = epoch*16
__device__ __forceinline__ void gsync_g(int gg, unsigned int target) {
    __syncthreads();
    __threadfence();
    if (threadIdx.x == 0) {
        atomicAdd(&g_ctrs[gg*32], 1u);
        volatile unsigned int* c = &g_ctrs[gg*32];
        while (*c < target) { }
        __threadfence();
    }
    __syncthreads();
}

// ---------------- init: degree-balanced node->CTA map ----------------
__global__ void k_init(const float* __restrict__ p) {
    __shared__ int cnt_s[NN];
    int n = threadIdx.x;
    int gb = (n >> 6) << 6;
    float px = p[n*3], py = p[n*3+1], pz = p[n*3+2];
    int cnt = 0;
    for (int j = 0; j < 64; j++) {
        int jg = gb + j;
        if (jg == n) continue;
        float dx = p[jg*3]-px, dy = p[jg*3+1]-py, dz = p[jg*3+2]-pz;
        if (dx*dx + dy*dy + dz*dz < 25.0f) cnt++;
    }
    cnt_s[n] = cnt;
    __syncthreads();
    int rank = 0;
    for (int j = 0; j < 64; j++) {
        int cj = cnt_s[gb + j];
        if (cj > cnt || (cj == cnt && (gb + j) < n)) rank++;
    }
    int round = rank >> 4, pos = rank & 15;
    int cta = (round & 1) ? (15 - pos) : pos;
    g_map[(((n >> 6)*16 + cta) << 2) + round] = n;
    g_p[0][n*3] = px; g_p[0][n*3+1] = py; g_p[0][n*3+2] = pz;
    if (n < 8) g_ctrs[n*32] = 0u;
}

__global__ void __launch_bounds__(TPB, 1)
k_fused(const float* __restrict__ s_in, const float* __restrict__ v_in,
        const float* __restrict__ p_in, const float* __restrict__ ea,
        const float* __restrict__ ln_g, const float* __restrict__ ln_b,
        const float* __restrict__ W1,  const float* __restrict__ b1,
        const float* __restrict__ W2,  const float* __restrict__ b2,
        const float* __restrict__ Wm1, const float* __restrict__ bm1,
        const float* __restrict__ Wm2, const float* __restrict__ bm2,
        const float* __restrict__ Wpre,const float* __restrict__ bpre,
        const float* __restrict__ Wpost,const float* __restrict__ bpost,
        float* __restrict__ out)
{
    extern __shared__ float sh[];
    int* shi = (int*)sh;
    const int tx   = threadIdx.x;
    const int grp  = tx >> 7;
    const int t128 = tx & 127;
    const int t    = tx & 63;
    const int lane = tx & 31;
    const int widx = tx >> 5;
    const bool lower = (t128 < 64);
    const int wrp  = t >> 5;
    const int gg   = blockIdx.x >> 4;
    const int cbase = gg << 6;
    const int i    = g_map[blockIdx.x*4 + grp];
    const int li   = i & 63;
    unsigned int epoch = 0;
    float* shHb = sh + SH_H + grp*140;

    float s_reg = s_in[i*SD + t];
    float v_reg = (t < 48) ? v_in[i*48 + t] : 0.0f;

    // -------- adjacency (lower 64 per node) --------
    if (lower) {
        float pix = p_in[i*3], piy = p_in[i*3+1], piz = p_in[i*3+2];
        int jg = cbase + t;
        float dx = p_in[jg*3]-pix, dy = p_in[jg*3+1]-piy, dz = p_in[jg*3+2]-piz;
        bool ok = (jg != i) && (dx*dx + dy*dy + dz*dz < 25.0f);
        unsigned m = __ballot_sync(0xffffffffu, ok);
        if (lane == 0) shi[SH_WCNT + grp*2 + wrp] = __popc(m);
        bar64(grp);
        int base = (wrp == 1) ? shi[SH_WCNT + grp*2] : 0;
        if (ok) shi[SH_NBR + grp*64 + base + __popc(m & ((1u << lane) - 1u))] = t;
        if (t == 0) {
            shi[SH_CNT + grp] = shi[SH_WCNT + grp*2] + shi[SH_WCNT + grp*2 + 1];
            shi[SH_LI + grp] = li;
        }
        bar64(grp);
    }
    __syncthreads();
    if (tx == 0) {
        int o = 0; shi[SH_OFF] = 0;
        #pragma unroll
        for (int n = 0; n < 4; n++) { o += shi[SH_CNT + n]; shi[SH_OFF + n + 1] = o; }
    }
    __syncthreads();
    const int cnt = shi[SH_CNT + grp];
    const float dinv = 1.0f / fmaxf((float)cnt, 1.0f);
    if (lower && t < cnt)
        shi[SH_IT + shi[SH_OFF + grp] + t] = (grp << 6) | shi[SH_NBR + grp*64 + t];
    __syncthreads();
    const int nit = shi[SH_OFF + 4];

    // E slice into smem
    for (int idx = tx; idx < nit*ED; idx += TPB) {
        int item = shi[SH_IT + (idx >> 4)];
        int c = idx & 15;
        int ig2 = item >> 6, j = item & 63;
        int lio = shi[SH_LI + ig2];
        int e = gg*EPG + lio*63 + j - (j > lio ? 1 : 0);
        sh[SH_EI + idx] = ea[(size_t)e*ED + c];
    }

    // -------- layers --------
    for (int l = 0; l < LL; l++) {
        const int pin = l & 1, pout = pin ^ 1;

        // ---- node_pre ----
        if (lower) {
            float xs = s_reg, xq = s_reg*s_reg;
            float xv = (t < 48) ? v_reg*v_reg : 0.0f;
            #pragma unroll
            for (int o = 16; o; o >>= 1) {
                xs += __shfl_down_sync(0xffffffffu, xs, o);
                xq += __shfl_down_sync(0xffffffffu, xq, o);
                xv += __shfl_down_sync(0xffffffffu, xv, o);
            }
            bar64(grp);
            if (lane == 0) {
                float* r = sh + SH_RED + grp*8 + wrp*3;
                r[0] = xs; r[1] = xq; r[2] = xv;
            }
            bar64(grp);
            const float* r = sh + SH_RED + grp*8;
            float mu   = (r[0] + r[3]) * (1.0f/64);
            float var  = (r[1] + r[4]) * (1.0f/64) - mu*mu;
            float vinv = rsqrtf((r[2] + r[5]) * (1.0f/16) + 1e-6f);
            s_reg = (s_reg - mu) * rsqrtf(fmaxf(var, 0.0f) + 1e-6f) * ln_g[l*SD + t] + ln_b[l*SD + t];
            shHb[t] = s_reg;
            if (t < 48) { v_reg *= vinv; g_vn[i*48 + t] = v_reg; }
            if (t < 3) {
                float p0 = g_p[pin][i*3], p1 = g_p[pin][i*3+1], p2 = g_p[pin][i*3+2];
                float inv = rsqrtf(p0*p0 + p1*p1 + p2*p2);
                g_pn[i*3 + t] = g_p[pin][i*3 + t] * inv;
            }
        }
        bar128(grp);
        {
            // ci/cj matvec reading W1 directly from global (L2-resident, coalesced)
            int which = t128 >> 6;
            const float* w1g = W1 + (size_t)l*146*SD + (size_t)which*64*SD;
            float a0 = which ? 0.0f : b1[l*SD + t];
            float a1 = 0.0f;
            #pragma unroll 8
            for (int k = 0; k < SD; k += 2) {
                a0 += shHb[k]   * __ldg(&w1g[k*64 + t]);
                a1 += shHb[k+1] * __ldg(&w1g[(k+1)*64 + t]);
            }
            float acc = a0 + a1;
            if (which == 0) sh[SH_CI + grp*64 + t] = acc;
            else            g_cj[i*SD + t] = acc;
        }

        // ---- stage ALL WEIGHTS pre-gsync (overlaps barrier wait) ----
        __syncthreads();   // node_post(l-1) reads of W1S/WPRE complete before overwrite
        {
            const float* w2g = W2 + (size_t)l*SD*DOUT;
            for (int idx = tx; idx < SD*DOUT; idx += TPB) {
                int kk = idx / DOUT, col = idx - kk*DOUT;
                float w = w2g[idx];
                if (col < 64) sh[SH_W2T + col*68 + kk] = w;
                else          sh[SH_W2T2 + (col-64)*68 + kk] = w;
            }
            for (int idx = tx; idx < 64*18; idx += TPB) {
                int col = idx / 18, row = idx - col*18;
                sh[SH_W1TT + col*20 + row] = W1[(size_t)l*146*SD + (128+row)*SD + col];
            }
            for (int idx = tx; idx < 33; idx += TPB)
                sh[SH_TB + idx] = b2[l*DOUT + 64 + idx];
            if (l > 0) {
                for (int idx = tx; idx < ED*ED; idx += TPB)
                    sh[SH_WPS + idx] = Wpost[(l-1)*ED*ED + idx];
            }
            if (l < LL-1) {
                const float4* m1 = (const float4*)(Wm1 + (size_t)l*SD*SD);
                const float4* m2 = (const float4*)(Wm2 + (size_t)l*SD*SD);
                float4* w1s = (float4*)(sh + SH_W1S);
                for (int idx = tx; idx < SD*SD/4; idx += TPB) {
                    w1s[idx] = m1[idx];
                    w1s[SD*SD/4 + idx] = m2[idx];
                }
            }
            const float4* wpg = (const float4*)(Wpre + (size_t)l*SD*ED);
            float4* wps = (float4*)(sh + SH_WPRE);
            for (int idx = tx; idx < SD*ED/4; idx += TPB) wps[idx] = wpg[idx];
        }

        gsync_g(gg, ++epoch * 16);   // group-local: cj/vn/pn/p(l) + f(l-1)

        // ---- stage DYNAMICS only (post-gsync) ----
        {
            const float4* cjg = (const float4*)(g_cj + cbase*SD);
            float4* cjs = (float4*)(sh + SH_CJ);
            for (int idx = tx; idx < 64*SD/4; idx += TPB) cjs[idx] = cjg[idx];
            if (l > 0) {
                const float4* vg = (const float4*)(g_vn + cbase*48);
                float4* vs = (float4*)(sh + SH_V);
                for (int idx = tx; idx < 64*48/4; idx += TPB) vs[idx] = vg[idx];
                const float4* fg = (const float4*)(g_f + cbase*ED);
                float4* fs = (float4*)(sh + SH_F);
                for (int idx = tx; idx < 64*ED/4; idx += TPB) fs[idx] = fg[idx];
            }
            for (int idx = tx; idx < 192; idx += TPB) {
                sh[SH_P + idx]  = g_p[pin][cbase*3 + idx];
                sh[SH_PN + idx] = g_pn[cbase*3 + idx];
            }
        }
        __syncthreads();

        // ---- pair phase with FUSED edge(l-1) update, flat items ----
        {
            float* hb = sh + SH_HW + widx*64;
            const float b2g = sh[SH_TB + 32];
            const int eidx = lane & 15;
            const float bpv = (l > 0) ? bpost[(l-1)*ED + eidx] : 0.0f;
            const float4* Ta4 = (const float4*)(sh + SH_W1TT + lane*20);
            const float4* Tb4 = (const float4*)(sh + SH_W1TT + (lane+32)*20);
            const float*  Ta  = sh + SH_W1TT + lane*20;
            const float*  Tb  = sh + SH_W1TT + (lane+32)*20;
            const float4* wc4 = (const float4*)(sh + SH_W2T2 + lane*68);

            for (int k = widx; k < nit; k += 16) {
                int item = shi[SH_IT + k];
                int ig2 = item >> 6, j = item & 63;
                int lio = shi[SH_LI + ig2];

                // --- fused edge update for layer l-1 (item-private E row) ---
                if (l > 0) {
                    float x = sh[SH_F + lio*ED + eidx] + sh[SH_F + j*ED + eidx];
                    float tv = sh[SH_EI + k*ED + eidx] + silu(x);
                    if (lane < 16) hb[eidx] = tv;
                    __syncwarp();
                    float4 T0 = ((const float4*)hb)[0];
                    float4 T1 = ((const float4*)hb)[1];
                    float4 T2 = ((const float4*)hb)[2];
                    float4 T3 = ((const float4*)hb)[3];
                    const float* wq = sh + SH_WPS;
                    float o = bpv
                        + T0.x*wq[0*16+eidx]  + T0.y*wq[1*16+eidx]
                        + T0.z*wq[2*16+eidx]  + T0.w*wq[3*16+eidx]
                        + T1.x*wq[4*16+eidx]  + T1.y*wq[5*16+eidx]
                        + T1.z*wq[6*16+eidx]  + T1.w*wq[7*16+eidx]
                        + T2.x*wq[8*16+eidx]  + T2.y*wq[9*16+eidx]
                        + T2.z*wq[10*16+eidx] + T2.w*wq[11*16+eidx]
                        + T3.x*wq[12*16+eidx] + T3.y*wq[13*16+eidx]
                        + T3.z*wq[14*16+eidx] + T3.w*wq[15*16+eidx];
                    __syncwarp();
                    if (lane < 16) sh[SH_EI + k*ED + eidx] = o;
                    __syncwarp();
                }

                float pix = sh[SH_P + lio*3], piy = sh[SH_P + lio*3+1], piz = sh[SH_P + lio*3+2];
                float dx = sh[SH_P + j*3]-pix, dy = sh[SH_P + j*3+1]-piy, dz = sh[SH_P + j*3+2]-piz;
                float dd = sqrtf(fmaxf(dx*dx + dy*dy + dz*dz, 1e-6f));
                float ac = sh[SH_PN + lio*3]*sh[SH_PN + j*3]
                         + sh[SH_PN + lio*3+1]*sh[SH_PN + j*3+1]
                         + sh[SH_PN + lio*3+2]*sh[SH_PN + j*3+2];
                float env = 0.5f*(__cosf(dd*0.62831853f) + 1.0f);
                float ri = 1.0f/(1.0f + dd);
                float rnx = dx*ri, rny = dy*ri, rnz = dz*ri;

                const float4* Ep = (const float4*)(sh + SH_EI + k*ED);
                float4 E0 = Ep[0], E1 = Ep[1], E2 = Ep[2], E3 = Ep[3];

                float hvA = sh[SH_CI + ig2*64 + lane]      + sh[SH_CJ + j*SD + lane];
                float hvB = sh[SH_CI + ig2*64 + 32 + lane] + sh[SH_CJ + j*SD + 32 + lane];
                {
                    float4 w0 = Ta4[0], w1 = Ta4[1], w2 = Ta4[2], w3 = Ta4[3];
                    hvA += dd*w0.x + ac*w0.y + E0.x*w0.z + E0.y*w0.w
                         + E0.z*w1.x + E0.w*w1.y + E1.x*w1.z + E1.y*w1.w
                         + E1.z*w2.x + E1.w*w2.y + E2.x*w2.z + E2.y*w2.w
                         + E2.z*w3.x + E2.w*w3.y + E3.x*w3.z + E3.y*w3.w
                         + E3.z*Ta[16] + E3.w*Ta[17];
                }
                {
                    float4 w0 = Tb4[0], w1 = Tb4[1], w2 = Tb4[2], w3 = Tb4[3];
                    hvB += dd*w0.x + ac*w0.y + E0.x*w0.z + E0.y*w0.w
                         + E0.z*w1.x + E0.w*w1.y + E1.x*w1.z + E1.y*w1.w
                         + E1.z*w2.x + E1.w*w2.y + E2.x*w2.z + E2.y*w2.w
                         + E2.z*w3.x + E2.w*w3.y + E3.x*w3.z + E3.y*w3.w
                         + E3.z*Tb[16] + E3.w*Tb[17];
                }
                float hpA = silu(hvA)*env;
                float hpB = silu(hvB)*env;

                float gcp = hpA*sh[SH_W2T2 + 32*68 + lane] + hpB*sh[SH_W2T2 + 32*68 + 32 + lane];
                #pragma unroll
                for (int o = 16; o; o >>= 1) gcp += __shfl_xor_sync(0xffffffffu, gcp, o);
                float gc = gcp + b2g*env;

                hb[lane] = hpA; hb[32 + lane] = hpB;
                __syncwarp();
                const float4* h4 = (const float4*)hb;
                float a0=0,a1=0,a2=0,a3=0;
                #pragma unroll
                for (int q = 0; q < 16; q++) {
                    float4 h = h4[q];
                    float4 w = wc4[q];
                    a0 += h.x*w.x; a1 += h.y*w.y;
                    a2 += h.z*w.z; a3 += h.w*w.w;
                }
                float tailv = (a0+a1)+(a2+a3) + sh[SH_TB + lane]*env;
                __syncwarp();

                int d = lane & 15;
                float gr = __shfl_sync(0xffffffffu, tailv, d);
                float gv = __shfl_sync(0xffffffffu, tailv, 16 + d);
                float rnA = (lane < 16) ? rnx : rny;
                float vA = rnA*gr;
                float vB = rnz*gr;
                if (l > 0) {
                    vA += sh[SH_V + j*48 + lane]*gv;
                    if (lane < 16) vB += sh[SH_V + j*48 + 32 + lane]*gv;
                }
                float* rec = sh + SH_REC + k*RS;
                rec[lane]      = hpA;
                rec[32 + lane] = hpB;
                rec[64 + lane] = vA;
                if (lane < 16) rec[96 + lane] = vB;
                if (lane < 3)  rec[112 + lane] = gc * ((lane==0)?rnx:((lane==1)?rny:rnz));
                if (lane == 0) rec[115] = env;
            }
        }
        __syncthreads();

        // ---- owner reduction across all 128 threads ----
        {
            int o0 = shi[SH_OFF + grp], o1 = shi[SH_OFF + grp + 1];
            float a0 = 0.0f, a1 = 0.0f;
            if (t128 < 116) {
                int k = o0;
                for (; k + 1 < o1; k += 2) {
                    a0 += sh[SH_REC + k*RS + t128];
                    a1 += sh[SH_REC + (k+1)*RS + t128];
                }
                if (k < o1) a0 += sh[SH_REC + k*RS + t128];
            }
            float acc = a0 + a1;
            if (lower) shHb[t] = acc;                                // henv
            else if (t128 < 116) sh[SH_AB + grp*52 + (t128-64)] = acc;
            bar128(grp);
            if (lower) {
                float envs = sh[SH_AB + grp*52 + 51];
                const float4* hs = (const float4*)shHb;
                const float4* wc = (const float4*)(sh + SH_W2T + t*68);
                float b0=0,b1v=0,b2v=0,b3=0;
                #pragma unroll
                for (int q = 0; q < 16; q++) {
                    float4 h4 = hs[q];
                    float4 w4 = wc[q];
                    b0 += h4.x*w4.x; b1v += h4.y*w4.y;
                    b2v += h4.z*w4.z; b3 += h4.w*w4.w;
                }
                s_reg += (b0+b1v)+(b2v+b3) + b2[l*DOUT + t]*envs;
                float accb = (t < 51) ? sh[SH_AB + grp*52 + t] : 0.0f;
                if (t < 48) v_reg += accb * dinv;
                if (t >= 48 && t < 51)
                    g_p[pout][i*3 + (t-48)] = sh[SH_P + li*3 + (t-48)] + accb * dinv;
            }
            bar128(grp);
        }

        // ---- node_post (lower 64 only) ----
        if (lower) {
            if (l < LL-1) {
                shHb[t] = s_reg;
                bar64(grp);
                const float* wm1 = sh + SH_W1S;
                float m0 = bm1[l*SD + t], m1 = 0.0f;
                #pragma unroll 8
                for (int kk = 0; kk < SD; kk += 2) {
                    m0 += shHb[kk]   * wm1[kk*SD + t];
                    m1 += shHb[kk+1] * wm1[(kk+1)*SD + t];
                }
                float hm = silu(m0 + m1);
                shHb[68 + t] = hm;
                bar64(grp);
                const float* wm2 = sh + SH_W1S + SD*SD;
                float q0 = bm2[l*SD + t], q1 = 0.0f;
                #pragma unroll 8
                for (int kk = 0; kk < SD; kk += 2) {
                    q0 += shHb[68+kk]   * wm2[kk*SD + t];
                    q1 += shHb[68+kk+1] * wm2[(kk+1)*SD + t];
                }
                s_reg += q0 + q1;
                bar64(grp);
            }
            shHb[t] = s_reg;
            bar64(grp);
            if (t < ED) {
                const float* wp = sh + SH_WPRE;
                float f0 = bpre[l*ED + t], f1 = 0.0f;
                #pragma unroll 8
                for (int kk = 0; kk < SD; kk += 2) {
                    f0 += shHb[kk]   * wp[kk*ED + t];
                    f1 += shHb[kk+1] * wp[(kk+1)*ED + t];
                }
                g_f[i*ED + t] = f0 + f1;
            }
        }
    }

    gsync_g(gg, ++epoch * 16);   // group-local: publish f(LL-1)

    // ---- final edge update ----
    {
        const float4* fg = (const float4*)(g_f + cbase*ED);
        float4* fs = (float4*)(sh + SH_F);
        for (int idx = tx; idx < 64*ED/4; idx += TPB) fs[idx] = fg[idx];
        for (int idx = tx; idx < ED*ED; idx += TPB)
            sh[SH_WPS + idx] = Wpost[(LL-1)*ED*ED + idx];
    }
    __syncthreads();
    {
        int hw = lane >> 4, e = lane & 15;
        float bp = bpost[(LL-1)*ED + e];
        for (int b = widx*2; b < nit; b += 32) {
            int k = b + hw;
            bool act = (k < nit);
            int sl = act ? k : 0;
            int item = shi[SH_IT + sl];
            int ig2 = item >> 6, j = item & 63;
            float x = sh[SH_F + shi[SH_LI + ig2]*ED + e] + sh[SH_F + j*ED + e];
            float tv = sh[SH_EI + sl*ED + e] + silu(x);
            float o = bp;
            #pragma unroll
            for (int m = 0; m < ED; m++) {
                float tm = __shfl_sync(0xffffffffu, tv, (hw << 4) + m);
                o += tm * sh[SH_WPS + m*ED + e];
            }
            if (act) sh[SH_EI + sl*ED + e] = o;
        }
    }
    __syncthreads();

    // -------- output --------
    if (lower) {
        out[i*SD + t] = s_reg;
        if (t < 48) out[OFF_V + i*48 + t] = v_reg;
        if (t < 3)  out[OFF_P + i*3 + t] = g_p[LL & 1][i*3 + t];
    }
    for (int idx = tx; idx < nit*ED; idx += TPB) {
        int item = shi[SH_IT + (idx >> 4)];
        int c = idx & 15;
        int ig2 = item >> 6, j = item & 63;
        int lio = shi[SH_LI + ig2];
        int e = gg*EPG + lio*63 + j - (j > lio ? 1 : 0);
        out[OFF_E + (size_t)e*ED + c] = sh[SH_EI + idx];
    }
    {
        const int e0 = blockIdx.x * (8*EPG / NCTA);
        for (int q = tx; q < (8*EPG/NCTA)*ED; q += TPB) {
            int e = e0 + (q >> 4), c = q & 15;
            int gg2 = e / EPG, rem = e - gg2*EPG;
            int si = rem / 63, t63 = rem - si*63;
            int ti = t63 + (t63 >= si ? 1 : 0);
            int a = gg2*64 + si, b = gg2*64 + ti;
            float dx = p_in[a*3]   - p_in[b*3];
            float dy = p_in[a*3+1] - p_in[b*3+1];
            float dz = p_in[a*3+2] - p_in[b*3+2];
            if (!(dx*dx + dy*dy + dz*dz < 25.0f))
                out[OFF_E + (size_t)e*ED + c] = ea[(size_t)e*ED + c];
        }
    }
}

// ---------------- launch ----------------
extern "C" void kernel_launch(void* const* d_in, const int* in_sizes, int n_in,
                              void* d_out, int out_size) {
    const float* s    = (const float*)d_in[0];
    const float* v    = (const float*)d_in[1];
    const float* p    = (const float*)d_in[2];
    const float* ea   = (const float*)d_in[3];
    const float* ln_g = (const float*)d_in[6];
    const float* ln_b = (const float*)d_in[7];
    const float* W1   = (const float*)d_in[8];
    const float* b1   = (const float*)d_in[9];
    const float* W2   = (const float*)d_in[10];
    const float* b2   = (const float*)d_in[11];
    const float* Wm1  = (const float*)d_in[12];
    const float* bm1  = (const float*)d_in[13];
    const float* Wm2  = (const float*)d_in[14];
    const float* bm2  = (const float*)d_in[15];
    const float* Wpre = (const float*)d_in[16];
    const float* bpre = (const float*)d_in[17];
    const float* Wpost= (const float*)d_in[18];
    const float* bpost= (const float*)d_in[19];
    float* out = (float*)d_out;

    cudaFuncSetAttribute(k_fused, cudaFuncAttributeMaxDynamicSharedMemorySize, SMEM_BYTES);
    k_init<<<1, NN>>>(p);
    k_fused<<<NCTA, TPB, SMEM_BYTES>>>(s, v, p, ea, ln_g, ln_b, W1, b1, W2, b2,
                                       Wm1, bm1, Wm2, bm2, Wpre, bpre, Wpost, bpost, out);
}

// round 16
// speedup vs baseline: 1.0528x; 1.0066x over previous
#include <cuda_runtime.h>
#include <math.h>

#define NN 512
#define SD 64
#define ED 16
#define LL 5
#define DOUT 97
#define EPG 4032
#define NCTA 128
#define TPB 512
#define RS 116

#define OFF_V (NN*SD)
#define OFF_E (OFF_V + NN*48)
#define OFF_P (OFF_E + 8*EPG*ED)

// ---- shared layout (float offsets) ----
#define SH_W2T   0        /* 64*68 */
#define SH_W2T2  4352     /* 33*68 */
#define SH_W1TT  6596     /* 64*20 : W1 tail per-col transposed */
#define SH_WPS   7876     /* 256 */
#define SH_W1S   8132     /* 8192 : Wm1|Wm2 (staged pre-gsync) */
#define SH_CJ    16324    /* 4096 */
#define SH_CI    20420    /* 256 */
#define SH_V     20676    /* 3072 */
#define SH_P     23748    /* 192 */
#define SH_PN    23940    /* 192 */
#define SH_F     24132    /* 1024 */
#define SH_TB    25156    /* 40 */
#define SH_H     25196    /* 4*140 */
#define SH_RED   25756    /* 32 */
#define SH_AB    25788    /* 4*52 */
#define SH_HW    25996    /* 16*64 */
#define SH_EI    27020    /* 4096 */
#define SH_REC   31116    /* 160*116 */
#define SH_IT    49676    /* 256 ints */
#define SH_NBR   49932    /* 256 ints */
#define SH_OFF   50188    /* 8 ints */
#define SH_CNT   50196    /* 4 ints */
#define SH_LI    50200    /* 4 ints */
#define SH_WCNT  50204    /* 8 ints */
#define SH_WPRE  50212    /* 1024 : Wpre own buffer */
#define SH_TOTAL 51236
#define SMEM_BYTES (SH_TOTAL*4)

// ---------------- device state ----------------
__device__ float g_cj[NN*SD];
__device__ float g_vn[NN*48];
__device__ float g_p[2][NN*3];
__device__ float g_pn[NN*3];
__device__ float g_f[NN*ED];
__device__ int   g_map[NN];
__device__ unsigned int g_ctrs[8*32];   // one counter per molecular group, 128B apart

__device__ __forceinline__ void bar64(int grp) {
    asm volatile("bar.sync %0, 64;" :: "r"(grp + 1) : "memory");
}
__device__ __forceinline__ void bar128(int grp) {
    asm volatile("bar.sync %0, 128;" :: "r"(grp + 5) : "memory");
}
__device__ __forceinline__ float silu(float x) {
    return x * (1.0f / (1.0f + __expf(-x)));
}
// per-molecular-group barrier: 16 CTAs arrive; target = epoch*16
__device__ __forceinline__ void gsync_g(int gg, unsigned int target) {
    __syncthreads();
    __threadfence();
    if (threadIdx.x == 0) {
        atomicAdd(&g_ctrs[gg*32], 1u);
        volatile unsigned int* c = &g_ctrs[gg*32];
        while (*c < target) { }
        __threadfence();
    }
    __syncthreads();
}

// ---------------- init: degree-balanced node->CTA map ----------------
__global__ void k_init(const float* __restrict__ p) {
    __shared__ int cnt_s[NN];
    int n = threadIdx.x;
    int gb = (n >> 6) << 6;
    float px = p[n*3], py = p[n*3+1], pz = p[n*3+2];
    int cnt = 0;
    for (int j = 0; j < 64; j++) {
        int jg = gb + j;
        if (jg == n) continue;
        float dx = p[jg*3]-px, dy = p[jg*3+1]-py, dz = p[jg*3+2]-pz;
        if (dx*dx + dy*dy + dz*dz < 25.0f) cnt++;
    }
    cnt_s[n] = cnt;
    __syncthreads();
    int rank = 0;
    for (int j = 0; j < 64; j++) {
        int cj = cnt_s[gb + j];
        if (cj > cnt || (cj == cnt && (gb + j) < n)) rank++;
    }
    int round = rank >> 4, pos = rank & 15;
    int cta = (round & 1) ? (15 - pos) : pos;
    g_map[(((n >> 6)*16 + cta) << 2) + round] = n;
    g_p[0][n*3] = px; g_p[0][n*3+1] = py; g_p[0][n*3+2] = pz;
    if (n < 8) g_ctrs[n*32] = 0u;
}

__global__ void __launch_bounds__(TPB, 1)
k_fused(const float* __restrict__ s_in, const float* __restrict__ v_in,
        const float* __restrict__ p_in, const float* __restrict__ ea,
        const float* __restrict__ ln_g, const float* __restrict__ ln_b,
        const float* __restrict__ W1,  const float* __restrict__ b1,
        const float* __restrict__ W2,  const float* __restrict__ b2,
        const float* __restrict__ Wm1, const float* __restrict__ bm1,
        const float* __restrict__ Wm2, const float* __restrict__ bm2,
        const float* __restrict__ Wpre,const float* __restrict__ bpre,
        const float* __restrict__ Wpost,const float* __restrict__ bpost,
        float* __restrict__ out)
{
    extern __shared__ float sh[];
    int* shi = (int*)sh;
    const int tx   = threadIdx.x;
    const int grp  = tx >> 7;
    const int t128 = tx & 127;
    const int t    = tx & 63;
    const int lane = tx & 31;
    const int widx = tx >> 5;
    const bool lower = (t128 < 64);
    const int wrp  = t >> 5;
    const int gg   = blockIdx.x >> 4;
    const int cbase = gg << 6;
    const int i    = g_map[blockIdx.x*4 + grp];
    const int li   = i & 63;
    unsigned int epoch = 0;
    float* shHb = sh + SH_H + grp*140;

    float s_reg = s_in[i*SD + t];
    float v_reg = (t < 48) ? v_in[i*48 + t] : 0.0f;

    // -------- adjacency (lower 64 per node) --------
    if (lower) {
        float pix = p_in[i*3], piy = p_in[i*3+1], piz = p_in[i*3+2];
        int jg = cbase + t;
        float dx = p_in[jg*3]-pix, dy = p_in[jg*3+1]-piy, dz = p_in[jg*3+2]-piz;
        bool ok = (jg != i) && (dx*dx + dy*dy + dz*dz < 25.0f);
        unsigned m = __ballot_sync(0xffffffffu, ok);
        if (lane == 0) shi[SH_WCNT + grp*2 + wrp] = __popc(m);
        bar64(grp);
        int base = (wrp == 1) ? shi[SH_WCNT + grp*2] : 0;
        if (ok) shi[SH_NBR + grp*64 + base + __popc(m & ((1u << lane) - 1u))] = t;
        if (t == 0) {
            shi[SH_CNT + grp] = shi[SH_WCNT + grp*2] + shi[SH_WCNT + grp*2 + 1];
            shi[SH_LI + grp] = li;
        }
        bar64(grp);
    }
    __syncthreads();
    if (tx == 0) {
        int o = 0; shi[SH_OFF] = 0;
        #pragma unroll
        for (int n = 0; n < 4; n++) { o += shi[SH_CNT + n]; shi[SH_OFF + n + 1] = o; }
    }
    __syncthreads();
    const int cnt = shi[SH_CNT + grp];
    const float dinv = 1.0f / fmaxf((float)cnt, 1.0f);
    if (lower && t < cnt)
        shi[SH_IT + shi[SH_OFF + grp] + t] = (grp << 6) | shi[SH_NBR + grp*64 + t];
    __syncthreads();
    const int nit = shi[SH_OFF + 4];

    // E slice into smem
    for (int idx = tx; idx < nit*ED; idx += TPB) {
        int item = shi[SH_IT + (idx >> 4)];
        int c = idx & 15;
        int ig2 = item >> 6, j = item & 63;
        int lio = shi[SH_LI + ig2];
        int e = gg*EPG + lio*63 + j - (j > lio ? 1 : 0);
        sh[SH_EI + idx] = ea[(size_t)e*ED + c];
    }

    // -------- layers --------
    for (int l = 0; l < LL; l++) {
        const int pin = l & 1, pout = pin ^ 1;

        // ---- node_pre ----
        if (lower) {
            float xs = s_reg, xq = s_reg*s_reg;
            float xv = (t < 48) ? v_reg*v_reg : 0.0f;
            #pragma unroll
            for (int o = 16; o; o >>= 1) {
                xs += __shfl_down_sync(0xffffffffu, xs, o);
                xq += __shfl_down_sync(0xffffffffu, xq, o);
                xv += __shfl_down_sync(0xffffffffu, xv, o);
            }
            if (lane == 0) {
                float* r = sh + SH_RED + grp*8 + wrp*3;
                r[0] = xs; r[1] = xq; r[2] = xv;
            }
            bar64(grp);
            const float* r = sh + SH_RED + grp*8;
            float mu   = (r[0] + r[3]) * (1.0f/64);
            float var  = (r[1] + r[4]) * (1.0f/64) - mu*mu;
            float vinv = rsqrtf((r[2] + r[5]) * (1.0f/16) + 1e-6f);
            s_reg = (s_reg - mu) * rsqrtf(fmaxf(var, 0.0f) + 1e-6f) * ln_g[l*SD + t] + ln_b[l*SD + t];
            shHb[t] = s_reg;
            if (t < 48) { v_reg *= vinv; g_vn[i*48 + t] = v_reg; }
            if (t < 3) {
                float p0 = g_p[pin][i*3], p1 = g_p[pin][i*3+1], p2 = g_p[pin][i*3+2];
                float inv = rsqrtf(p0*p0 + p1*p1 + p2*p2);
                g_pn[i*3 + t] = g_p[pin][i*3 + t] * inv;
            }
        }
        bar128(grp);
        {
            // ci/cj matvec reading W1 directly from global (L2-resident, coalesced)
            int which = t128 >> 6;
            const float* w1g = W1 + (size_t)l*146*SD + (size_t)which*64*SD;
            float a0 = which ? 0.0f : b1[l*SD + t];
            float a1 = 0.0f;
            #pragma unroll 8
            for (int k = 0; k < SD; k += 2) {
                a0 += shHb[k]   * __ldg(&w1g[k*64 + t]);
                a1 += shHb[k+1] * __ldg(&w1g[(k+1)*64 + t]);
            }
            float acc = a0 + a1;
            if (which == 0) sh[SH_CI + grp*64 + t] = acc;
            else            g_cj[i*SD + t] = acc;
        }

        // ---- stage ALL WEIGHTS pre-gsync (overlaps barrier wait) ----
        __syncthreads();   // node_post(l-1) reads of W1S/WPRE complete before overwrite
        {
            const float* w2g = W2 + (size_t)l*SD*DOUT;
            for (int idx = tx; idx < SD*DOUT; idx += TPB) {
                int kk = idx / DOUT, col = idx - kk*DOUT;
                float w = w2g[idx];
                if (col < 64) sh[SH_W2T + col*68 + kk] = w;
                else          sh[SH_W2T2 + (col-64)*68 + kk] = w;
            }
            for (int idx = tx; idx < 64*18; idx += TPB) {
                int col = idx / 18, row = idx - col*18;
                sh[SH_W1TT + col*20 + row] = W1[(size_t)l*146*SD + (128+row)*SD + col];
            }
            for (int idx = tx; idx < 33; idx += TPB)
                sh[SH_TB + idx] = b2[l*DOUT + 64 + idx];
            if (l > 0) {
                for (int idx = tx; idx < ED*ED; idx += TPB)
                    sh[SH_WPS + idx] = Wpost[(l-1)*ED*ED + idx];
            }
            if (l < LL-1) {
                const float4* m1 = (const float4*)(Wm1 + (size_t)l*SD*SD);
                const float4* m2 = (const float4*)(Wm2 + (size_t)l*SD*SD);
                float4* w1s = (float4*)(sh + SH_W1S);
                for (int idx = tx; idx < SD*SD/4; idx += TPB) {
                    w1s[idx] = m1[idx];
                    w1s[SD*SD/4 + idx] = m2[idx];
                }
            }
            const float4* wpg = (const float4*)(Wpre + (size_t)l*SD*ED);
            float4* wps = (float4*)(sh + SH_WPRE);
            for (int idx = tx; idx < SD*ED/4; idx += TPB) wps[idx] = wpg[idx];
        }

        gsync_g(gg, ++epoch * 16);   // group-local: cj/vn/pn/p(l) + f(l-1)

        // ---- stage DYNAMICS only (post-gsync) ----
        {
            const float4* cjg = (const float4*)(g_cj + cbase*SD);
            float4* cjs = (float4*)(sh + SH_CJ);
            for (int idx = tx; idx < 64*SD/4; idx += TPB) cjs[idx] = cjg[idx];
            if (l > 0) {
                const float4* vg = (const float4*)(g_vn + cbase*48);
                float4* vs = (float4*)(sh + SH_V);
                for (int idx = tx; idx < 64*48/4; idx += TPB) vs[idx] = vg[idx];
                const float4* fg = (const float4*)(g_f + cbase*ED);
                float4* fs = (float4*)(sh + SH_F);
                for (int idx = tx; idx < 64*ED/4; idx += TPB) fs[idx] = fg[idx];
            }
            for (int idx = tx; idx < 192; idx += TPB) {
                sh[SH_P + idx]  = g_p[pin][cbase*3 + idx];
                sh[SH_PN + idx] = g_pn[cbase*3 + idx];
            }
        }
        __syncthreads();

        // ---- pair phase with FUSED edge(l-1) update, flat items ----
        {
            float* hb = sh + SH_HW + widx*64;
            const float b2g = sh[SH_TB + 32];
            const int eidx = lane & 15;
            const float bpv = (l > 0) ? bpost[(l-1)*ED + eidx] : 0.0f;
            const float4* Ta4 = (const float4*)(sh + SH_W1TT + lane*20);
            const float4* Tb4 = (const float4*)(sh + SH_W1TT + (lane+32)*20);
            const float*  Ta  = sh + SH_W1TT + lane*20;
            const float*  Tb  = sh + SH_W1TT + (lane+32)*20;
            const float4* wc4 = (const float4*)(sh + SH_W2T2 + lane*68);

            for (int k = widx; k < nit; k += 16) {
                int item = shi[SH_IT + k];
                int ig2 = item >> 6, j = item & 63;
                int lio = shi[SH_LI + ig2];

                // --- fused edge update for layer l-1 (item-private E row) ---
                if (l > 0) {
                    float x = sh[SH_F + lio*ED + eidx] + sh[SH_F + j*ED + eidx];
                    float tv = sh[SH_EI + k*ED + eidx] + silu(x);
                    if (lane < 16) hb[eidx] = tv;
                    __syncwarp();
                    float4 T0 = ((const float4*)hb)[0];
                    float4 T1 = ((const float4*)hb)[1];
                    float4 T2 = ((const float4*)hb)[2];
                    float4 T3 = ((const float4*)hb)[3];
                    const float* wq = sh + SH_WPS;
                    float o = bpv
                        + T0.x*wq[0*16+eidx]  + T0.y*wq[1*16+eidx]
                        + T0.z*wq[2*16+eidx]  + T0.w*wq[3*16+eidx]
                        + T1.x*wq[4*16+eidx]  + T1.y*wq[5*16+eidx]
                        + T1.z*wq[6*16+eidx]  + T1.w*wq[7*16+eidx]
                        + T2.x*wq[8*16+eidx]  + T2.y*wq[9*16+eidx]
                        + T2.z*wq[10*16+eidx] + T2.w*wq[11*16+eidx]
                        + T3.x*wq[12*16+eidx] + T3.y*wq[13*16+eidx]
                        + T3.z*wq[14*16+eidx] + T3.w*wq[15*16+eidx];
                    __syncwarp();
                    if (lane < 16) sh[SH_EI + k*ED + eidx] = o;
                    __syncwarp();
                }

                float pix = sh[SH_P + lio*3], piy = sh[SH_P + lio*3+1], piz = sh[SH_P + lio*3+2];
                float dx = sh[SH_P + j*3]-pix, dy = sh[SH_P + j*3+1]-piy, dz = sh[SH_P + j*3+2]-piz;
                float dd = sqrtf(fmaxf(dx*dx + dy*dy + dz*dz, 1e-6f));
                float ac = sh[SH_PN + lio*3]*sh[SH_PN + j*3]
                         + sh[SH_PN + lio*3+1]*sh[SH_PN + j*3+1]
                         + sh[SH_PN + lio*3+2]*sh[SH_PN + j*3+2];
                float env = 0.5f*(__cosf(dd*0.62831853f) + 1.0f);
                float ri = 1.0f/(1.0f + dd);
                float rnx = dx*ri, rny = dy*ri, rnz = dz*ri;

                const float4* Ep = (const float4*)(sh + SH_EI + k*ED);
                float4 E0 = Ep[0], E1 = Ep[1], E2 = Ep[2], E3 = Ep[3];

                float hvA = sh[SH_CI + ig2*64 + lane]      + sh[SH_CJ + j*SD + lane];
                float hvB = sh[SH_CI + ig2*64 + 32 + lane] + sh[SH_CJ + j*SD + 32 + lane];
                {
                    float4 w0 = Ta4[0], w1 = Ta4[1], w2 = Ta4[2], w3 = Ta4[3];
                    hvA += dd*w0.x + ac*w0.y + E0.x*w0.z + E0.y*w0.w
                         + E0.z*w1.x + E0.w*w1.y + E1.x*w1.z + E1.y*w1.w
                         + E1.z*w2.x + E1.w*w2.y + E2.x*w2.z + E2.y*w2.w
                         + E2.z*w3.x + E2.w*w3.y + E3.x*w3.z + E3.y*w3.w
                         + E3.z*Ta[16] + E3.w*Ta[17];
                }
                {
                    float4 w0 = Tb4[0], w1 = Tb4[1], w2 = Tb4[2], w3 = Tb4[3];
                    hvB += dd*w0.x + ac*w0.y + E0.x*w0.z + E0.y*w0.w
                         + E0.z*w1.x + E0.w*w1.y + E1.x*w1.z + E1.y*w1.w
                         + E1.z*w2.x + E1.w*w2.y + E2.x*w2.z + E2.y*w2.w
                         + E2.z*w3.x + E2.w*w3.y + E3.x*w3.z + E3.y*w3.w
                         + E3.z*Tb[16] + E3.w*Tb[17];
                }
                float hpA = silu(hvA)*env;
                float hpB = silu(hvB)*env;

                float gcp = hpA*sh[SH_W2T2 + 32*68 + lane] + hpB*sh[SH_W2T2 + 32*68 + 32 + lane];
                #pragma unroll
                for (int o = 16; o; o >>= 1) gcp += __shfl_xor_sync(0xffffffffu, gcp, o);
                float gc = gcp + b2g*env;

                hb[lane] = hpA; hb[32 + lane] = hpB;
                __syncwarp();
                const float4* h4 = (const float4*)hb;
                float a0=0,a1=0,a2=0,a3=0;
                #pragma unroll
                for (int q = 0; q < 16; q++) {
                    float4 h = h4[q];
                    float4 w = wc4[q];
                    a0 += h.x*w.x; a1 += h.y*w.y;
                    a2 += h.z*w.z; a3 += h.w*w.w;
                }
                float tailv = (a0+a1)+(a2+a3) + sh[SH_TB + lane]*env;
                __syncwarp();

                int d = lane & 15;
                float gr = __shfl_sync(0xffffffffu, tailv, d);
                float gv = __shfl_sync(0xffffffffu, tailv, 16 + d);
                float rnA = (lane < 16) ? rnx : rny;
                float vA = rnA*gr;
                float vB = rnz*gr;
                if (l > 0) {
                    vA += sh[SH_V + j*48 + lane]*gv;
                    if (lane < 16) vB += sh[SH_V + j*48 + 32 + lane]*gv;
                }
                float* rec = sh + SH_REC + k*RS;
                rec[lane]      = hpA;
                rec[32 + lane] = hpB;
                rec[64 + lane] = vA;
                if (lane < 16) rec[96 + lane] = vB;
                if (lane < 3)  rec[112 + lane] = gc * ((lane==0)?rnx:((lane==1)?rny:rnz));
                if (lane == 0) rec[115] = env;
            }
        }
        __syncthreads();

        // ---- owner reduction across all 128 threads ----
        {
            int o0 = shi[SH_OFF + grp], o1 = shi[SH_OFF + grp + 1];
            float a0 = 0.0f, a1 = 0.0f;
            if (t128 < 116) {
                int k = o0;
                for (; k + 1 < o1; k += 2) {
                    a0 += sh[SH_REC + k*RS + t128];
                    a1 += sh[SH_REC + (k+1)*RS + t128];
                }
                if (k < o1) a0 += sh[SH_REC + k*RS + t128];
            }
            float acc = a0 + a1;
            if (lower) shHb[t] = acc;                                // henv
            else if (t128 < 116) sh[SH_AB + grp*52 + (t128-64)] = acc;
            bar128(grp);
            if (lower) {
                float envs = sh[SH_AB + grp*52 + 51];
                const float4* hs = (const float4*)shHb;
                const float4* wc = (const float4*)(sh + SH_W2T + t*68);
                float b0=0,b1v=0,b2v=0,b3=0;
                #pragma unroll
                for (int q = 0; q < 16; q++) {
                    float4 h4 = hs[q];
                    float4 w4 = wc[q];
                    b0 += h4.x*w4.x; b1v += h4.y*w4.y;
                    b2v += h4.z*w4.z; b3 += h4.w*w4.w;
                }
                s_reg += (b0+b1v)+(b2v+b3) + b2[l*DOUT + t]*envs;
                float accb = (t < 51) ? sh[SH_AB + grp*52 + t] : 0.0f;
                if (t < 48) v_reg += accb * dinv;
                if (t >= 48 && t < 51)
                    g_p[pout][i*3 + (t-48)] = sh[SH_P + li*3 + (t-48)] + accb * dinv;
            }
            // (2nd bar128 removed: node_post now stages in shHb[68..], disjoint
            //  from gs-matvec reads of shHb[0..63])
        }

        // ---- node_post (lower 64 only; staging in shHb[68..131]) ----
        if (lower) {
            if (l < LL-1) {
                shHb[68 + t] = s_reg;
                bar64(grp);
                const float* wm1 = sh + SH_W1S;
                float m0 = bm1[l*SD + t], m1 = 0.0f;
                #pragma unroll 8
                for (int kk = 0; kk < SD; kk += 2) {
                    m0 += shHb[68+kk]   * wm1[kk*SD + t];
                    m1 += shHb[68+kk+1] * wm1[(kk+1)*SD + t];
                }
                shHb[t] = silu(m0 + m1);
                bar64(grp);
                const float* wm2 = sh + SH_W1S + SD*SD;
                float q0 = bm2[l*SD + t], q1 = 0.0f;
                #pragma unroll 8
                for (int kk = 0; kk < SD; kk += 2) {
                    q0 += shHb[kk]   * wm2[kk*SD + t];
                    q1 += shHb[kk+1] * wm2[(kk+1)*SD + t];
                }
                s_reg += q0 + q1;
            }
            shHb[68 + t] = s_reg;
            bar64(grp);
            if (t < ED) {
                const float* wp = sh + SH_WPRE;
                float f0 = bpre[l*ED + t], f1 = 0.0f;
                #pragma unroll 8
                for (int kk = 0; kk < SD; kk += 2) {
                    f0 += shHb[68+kk]   * wp[kk*ED + t];
                    f1 += shHb[68+kk+1] * wp[(kk+1)*ED + t];
                }
                g_f[i*ED + t] = f0 + f1;
            }
        }
    }

    gsync_g(gg, ++epoch * 16);   // group-local: publish f(LL-1)

    // ---- final edge update ----
    {
        const float4* fg = (const float4*)(g_f + cbase*ED);
        float4* fs = (float4*)(sh + SH_F);
        for (int idx = tx; idx < 64*ED/4; idx += TPB) fs[idx] = fg[idx];
        for (int idx = tx; idx < ED*ED; idx += TPB)
            sh[SH_WPS + idx] = Wpost[(LL-1)*ED*ED + idx];
    }
    __syncthreads();
    {
        int hw = lane >> 4, e = lane & 15;
        float bp = bpost[(LL-1)*ED + e];
        for (int b = widx*2; b < nit; b += 32) {
            int k = b + hw;
            bool act = (k < nit);
            int sl = act ? k : 0;
            int item = shi[SH_IT + sl];
            int ig2 = item >> 6, j = item & 63;
            float x = sh[SH_F + shi[SH_LI + ig2]*ED + e] + sh[SH_F + j*ED + e];
            float tv = sh[SH_EI + sl*ED + e] + silu(x);
            float o = bp;
            #pragma unroll
            for (int m = 0; m < ED; m++) {
                float tm = __shfl_sync(0xffffffffu, tv, (hw << 4) + m);
                o += tm * sh[SH_WPS + m*ED + e];
            }
            if (act) sh[SH_EI + sl*ED + e] = o;
        }
    }
    __syncthreads();

    // -------- output --------
    if (lower) {
        out[i*SD + t] = s_reg;
        if (t < 48) out[OFF_V + i*48 + t] = v_reg;
        if (t < 3)  out[OFF_P + i*3 + t] = g_p[LL & 1][i*3 + t];
    }
    for (int idx = tx; idx < nit*ED; idx += TPB) {
        int item = shi[SH_IT + (idx >> 4)];
        int c = idx & 15;
        int ig2 = item >> 6, j = item & 63;
        int lio = shi[SH_LI + ig2];
        int e = gg*EPG + lio*63 + j - (j > lio ? 1 : 0);
        out[OFF_E + (size_t)e*ED + c] = sh[SH_EI + idx];
    }
    {
        const int e0 = blockIdx.x * (8*EPG / NCTA);
        for (int q = tx; q < (8*EPG/NCTA)*ED; q += TPB) {
            int e = e0 + (q >> 4), c = q & 15;
            int gg2 = e / EPG, rem = e - gg2*EPG;
            int si = rem / 63, t63 = rem - si*63;
            int ti = t63 + (t63 >= si ? 1 : 0);
            int a = gg2*64 + si, b = gg2*64 + ti;
            float dx = p_in[a*3]   - p_in[b*3];
            float dy = p_in[a*3+1] - p_in[b*3+1];
            float dz = p_in[a*3+2] - p_in[b*3+2];
            if (!(dx*dx + dy*dy + dz*dz < 25.0f))
                out[OFF_E + (size_t)e*ED + c] = ea[(size_t)e*ED + c];
        }
    }
}

// ---------------- launch ----------------
extern "C" void kernel_launch(void* const* d_in, const int* in_sizes, int n_in,
                              void* d_out, int out_size) {
    const float* s    = (const float*)d_in[0];
    const float* v    = (const float*)d_in[1];
    const float* p    = (const float*)d_in[2];
    const float* ea   = (const float*)d_in[3];
    const float* ln_g = (const float*)d_in[6];
    const float* ln_b = (const float*)d_in[7];
    const float* W1   = (const float*)d_in[8];
    const float* b1   = (const float*)d_in[9];
    const float* W2   = (const float*)d_in[10];
    const float* b2   = (const float*)d_in[11];
    const float* Wm1  = (const float*)d_in[12];
    const float* bm1  = (const float*)d_in[13];
    const float* Wm2  = (const float*)d_in[14];
    const float* bm2  = (const float*)d_in[15];
    const float* Wpre = (const float*)d_in[16];
    const float* bpre = (const float*)d_in[17];
    const float* Wpost= (const float*)d_in[18];
    const float* bpost= (const float*)d_in[19];
    float* out = (float*)d_out;

    cudaFuncSetAttribute(k_fused, cudaFuncAttributeMaxDynamicSharedMemorySize, SMEM_BYTES);
    k_init<<<1, NN>>>(p);
    k_fused<<<NCTA, TPB, SMEM_BYTES>>>(s, v, p, ea, ln_g, ln_b, W1, b1, W2, b2,
                                       Wm1, bm1, Wm2, bm2, Wpre, bpre, Wpost, bpost, out);
}